// round 11
// baseline (speedup 1.0000x reference)
#include <cuda_runtime.h>
#include <cuda_bf16.h>
#include <math_constants.h>
#include <cstdint>

// ---------------- problem constants ----------------
#define NNODES 20000
#define NEDGES 320000
#define ETOT   (NEDGES + NNODES)   // + self loops
#define CIN    256
#define CHID   256
#define COUT   128
#define NEG_SLOPE 0.2f
#define NBLK_N ((NNODES + 255) / 256)   // 79

// ---------------- device scratch (no allocations allowed) ----------------
__device__ float g_h[NNODES * CHID];     // GEMM output of current layer
__device__ float g_as1[NNODES];
__device__ float g_ad1[NNODES];
__device__ float g_as2[NNODES];
__device__ float g_ad2[NNODES];
__device__ int   g_deg[NNODES];
__device__ int   g_bsum[NBLK_N];
__device__ int   g_off[NNODES + 1];
__device__ int   g_cur[NNODES];
__device__ int   g_srcs[ETOT];
__device__ int   g_esrc[ETOT];
__device__ int   g_edst[ETOT];
__device__ int   g_is64;

// bf16 split operands for tensor-core GEMMs
__device__ __nv_bfloat16 g_xhi[NNODES * CIN];
__device__ __nv_bfloat16 g_xlo[NNODES * CIN];
__device__ __nv_bfloat16 g_thi[NNODES * CHID];   // layer-2 input (written by aggregate1)
__device__ __nv_bfloat16 g_tlo[NNODES * CHID];
__device__ __nv_bfloat16 g_w1hi[CHID * CIN];     // W1^T : [N=CHID][K=CIN]
__device__ __nv_bfloat16 g_w1lo[CHID * CIN];
__device__ __nv_bfloat16 g_w2hi[COUT * CHID];    // W2^T : [N=COUT][K=CHID]
__device__ __nv_bfloat16 g_w2lo[COUT * CHID];

// ---------------- PDL helpers (no-ops when not PDL-launched) ----------------
__device__ __forceinline__ void pdl_trigger() {
    asm volatile("griddepcontrol.launch_dependents;" ::: "memory");
}
__device__ __forceinline__ void pdl_wait() {
    asm volatile("griddepcontrol.wait;" ::: "memory");
}

// ---------------- split helper ----------------
__device__ __forceinline__ void bf16_split(float v, __nv_bfloat16& hi, __nv_bfloat16& lo) {
    hi = __float2bfloat16(v);
    lo = __float2bfloat16(v - __bfloat162float(hi));
}

// ---------------- detect dtype + zero init (merged) ----------------
__global__ void detect_init_kernel(const void* __restrict__ ei) {
    int i = blockIdx.x * blockDim.x + threadIdx.x;
    if (i < NNODES) {
        g_deg[i] = 0;
        g_as1[i] = 0.f; g_ad1[i] = 0.f;
        g_as2[i] = 0.f; g_ad2[i] = 0.f;
    }
    if (blockIdx.x == 0) {
        const long long* p = (const long long*)ei;
        int bad = 0;
        #pragma unroll
        for (int k = threadIdx.x; k < 2048; k += 256) {
            long long v = p[k];
            if (v < 0 || v >= NNODES) bad = 1;
        }
        int anybad = __syncthreads_or(bad);
        if (threadIdx.x == 0) g_is64 = !anybad;
    }
}

// ---------------- convert x + W1 + W2 to bf16 hi/lo (one kernel) ----------------
__global__ void conv_all_kernel(const float* __restrict__ x,
                                const float* __restrict__ W1,
                                const float* __restrict__ W2) {
    int i = blockIdx.x * blockDim.x + threadIdx.x;
    if (i < NNODES * CIN) {
        bf16_split(x[i], g_xhi[i], g_xlo[i]);
        return;
    }
    i -= NNODES * CIN;
    if (i < CIN * CHID) {
        int k = i / CHID, n = i % CHID;           // W1[k][n] -> w1t[n][k]
        bf16_split(W1[i], g_w1hi[n * CIN + k], g_w1lo[n * CIN + k]);
        return;
    }
    i -= CIN * CHID;
    if (i < CHID * COUT) {
        int k = i / COUT, n = i % COUT;           // W2[k][n] -> w2t[n][k]
        bf16_split(W2[i], g_w2hi[n * CHID + k], g_w2lo[n * CHID + k]);
    }
}

// ---------------- convert + degree count ----------------
__global__ void convert_count_kernel(const void* __restrict__ ei) {
    int e = blockIdx.x * blockDim.x + threadIdx.x;
    if (e >= ETOT) return;
    int s, d;
    if (e < NEDGES) {
        if (g_is64) {
            const long long* p = (const long long*)ei;
            s = (int)p[e]; d = (int)p[NEDGES + e];
        } else {
            const int* p = (const int*)ei;
            s = p[e]; d = p[NEDGES + e];
        }
    } else {
        s = e - NEDGES; d = s;
    }
    g_esrc[e] = s;
    g_edst[e] = d;
    atomicAdd(&g_deg[d], 1);
}

// ---------------- multi-block scan ----------------
__global__ void scan_part_kernel() {
    __shared__ int sh[256];
    int i = blockIdx.x * 256 + threadIdx.x;
    sh[threadIdx.x] = (i < NNODES) ? g_deg[i] : 0;
    __syncthreads();
    #pragma unroll
    for (int st = 128; st > 0; st >>= 1) {
        if (threadIdx.x < st) sh[threadIdx.x] += sh[threadIdx.x + st];
        __syncthreads();
    }
    if (threadIdx.x == 0) g_bsum[blockIdx.x] = sh[0];
}

__global__ void scan_write_kernel() {
    __shared__ int sh[256];
    __shared__ int base_sh;
    const int t = threadIdx.x;
    const int b = blockIdx.x;
    int pv = (t < b && t < NBLK_N) ? g_bsum[t] : 0;
    sh[t] = pv;
    __syncthreads();
    #pragma unroll
    for (int st = 128; st > 0; st >>= 1) {
        if (t < st) sh[t] += sh[t + st];
        __syncthreads();
    }
    if (t == 0) base_sh = sh[0];
    __syncthreads();
    const int base = base_sh;
    __syncthreads();
    int i = b * 256 + t;
    int d = (i < NNODES) ? g_deg[i] : 0;
    sh[t] = d;
    __syncthreads();
    #pragma unroll
    for (int st = 1; st < 256; st <<= 1) {
        int v = (t >= st) ? sh[t - st] : 0;
        __syncthreads();
        sh[t] += v;
        __syncthreads();
    }
    if (i < NNODES) {
        int off = base + sh[t] - d;
        g_off[i] = off;
        g_cur[i] = off;
    }
    if (b == NBLK_N - 1 && t == 255) g_off[NNODES] = base + sh[255];
}

__global__ void fill_kernel() {
    int e = blockIdx.x * blockDim.x + threadIdx.x;
    if (e >= ETOT) return;
    int pos = atomicAdd(&g_cur[g_edst[e]], 1);
    g_srcs[pos] = g_esrc[e];
}

// ---------------- bf16-split warp MMA GEMM, cp.async double-buffered ----------------
// C[M x NC] = (Ahi+Alo)[M x K] @ ((Bhi+Blo)[NC x K])^T, 3 combos, fp32 accum.
// CTA tile 128 x BN, 8 warps (4 m x 2 n), warp tile 32 x BN/2, mma m16n8k16.
// Fused epilogue: atomicAdd partial alpha_src/alpha_dst dots per row.
#define KC    32
#define KPAD  40                          // 80B row stride, conflict-free fragments
#define ABYTES (128 * KPAD * 2)           // 10240

__device__ __forceinline__ void mma16816(float* c, const uint32_t* a, const uint32_t* b) {
    asm volatile(
        "mma.sync.aligned.m16n8k16.row.col.f32.bf16.bf16.f32 "
        "{%0,%1,%2,%3}, {%4,%5,%6,%7}, {%8,%9}, {%0,%1,%2,%3};"
        : "+f"(c[0]), "+f"(c[1]), "+f"(c[2]), "+f"(c[3])
        : "r"(a[0]), "r"(a[1]), "r"(a[2]), "r"(a[3]), "r"(b[0]), "r"(b[1]));
}

__device__ __forceinline__ uint32_t smem_u32(const void* p) {
    uint32_t a;
    asm("{ .reg .u64 t; cvta.to.shared.u64 t, %1; cvt.u32.u64 %0, t; }" : "=r"(a) : "l"(p));
    return a;
}
__device__ __forceinline__ void cp16(uint32_t dst, const void* src) {
    asm volatile("cp.async.cg.shared.global [%0], [%1], 16;" :: "r"(dst), "l"(src));
}

template <int NC, int BN>
__global__ __launch_bounds__(256)
void gemm_mma_kernel(const __nv_bfloat16* __restrict__ Ahi, const __nv_bfloat16* __restrict__ Alo,
                     const __nv_bfloat16* __restrict__ Bhi, const __nv_bfloat16* __restrict__ Blo,
                     float* __restrict__ C,
                     const float* __restrict__ avs, const float* __restrict__ avd,
                     float* __restrict__ as_out, float* __restrict__ ad_out,
                     int M, int K) {
    constexpr int NT      = BN / 16;            // n-tiles per warp
    constexpr int BBYTES  = BN * KPAD * 2;
    constexpr int BUFB    = 2 * ABYTES + 2 * BBYTES;

    extern __shared__ char smem[];
    const uint32_t sb = smem_u32(smem);

    const int tid   = threadIdx.x;
    const int wid   = tid >> 5;
    const int lane  = tid & 31;
    const int wm    = wid & 3;
    const int wn    = wid >> 2;
    const int g     = lane >> 2;
    const int t     = lane & 3;
    const int m0    = blockIdx.y * 128;
    const int n0    = blockIdx.x * BN;

    pdl_trigger();          // let dependent kernel launch early
    pdl_wait();             // inputs may come from the immediately preceding kernel

    float acc[2][NT][4];
    #pragma unroll
    for (int i = 0; i < 2; i++)
        #pragma unroll
        for (int j = 0; j < NT; j++)
            #pragma unroll
            for (int q = 0; q < 4; q++) acc[i][j][q] = 0.0f;

    const int NCHUNK = K / KC;

    auto issue_chunk = [&](int ch, int buf) {
        const int kc0 = ch * KC;
        const uint32_t bbase = sb + buf * BUFB;
        #pragma unroll
        for (int it = 0; it < 2; it++) {                // A: 128 rows x 4 slots
            const int idx = tid + it * 256;
            const int row = idx >> 2;
            const int c4  = idx & 3;
            const int arow = min(m0 + row, M - 1);      // clamp; garbage rows unsaved
            const size_t ao = (size_t)arow * K + kc0 + c4 * 8;
            const uint32_t so = (uint32_t)(row * (KPAD * 2) + c4 * 16);
            cp16(bbase + so, Ahi + ao);
            cp16(bbase + ABYTES + so, Alo + ao);
        }
        #pragma unroll
        for (int it = 0; it < BN * 4 / 256; it++) {     // B: BN rows x 4 slots
            const int idx = tid + it * 256;
            const int row = idx >> 2;
            const int c4  = idx & 3;
            const size_t bo = (size_t)(n0 + row) * K + kc0 + c4 * 8;  // NC mult of BN
            const uint32_t so = (uint32_t)(row * (KPAD * 2) + c4 * 16);
            cp16(bbase + 2 * ABYTES + so, Bhi + bo);
            cp16(bbase + 2 * ABYTES + BBYTES + so, Blo + bo);
        }
        asm volatile("cp.async.commit_group;" ::: "memory");
    };

    issue_chunk(0, 0);

    for (int ch = 0; ch < NCHUNK; ch++) {
        const int buf = ch & 1;
        const bool more = (ch + 1 < NCHUNK);
        if (more) issue_chunk(ch + 1, buf ^ 1);
        if (more) asm volatile("cp.async.wait_group 1;" ::: "memory");
        else      asm volatile("cp.async.wait_group 0;" ::: "memory");
        __syncthreads();

        const char* pbuf = smem + buf * BUFB;
        #pragma unroll
        for (int ks = 0; ks < KC / 16; ks++) {
            const int kb = ks * 16;
            #pragma unroll
            for (int combo = 0; combo < 3; combo++) {
                const char* pA = pbuf + ((combo == 2) ? ABYTES : 0);
                const char* pB = pbuf + 2 * ABYTES + ((combo == 1) ? BBYTES : 0);

                uint32_t afrag[2][4];
                #pragma unroll
                for (int mt = 0; mt < 2; mt++) {
                    const int r0 = wm * 32 + mt * 16 + g;
                    const char* q0 = pA + r0 * (KPAD * 2) + (kb + 2 * t) * 2;
                    const char* q1 = pA + (r0 + 8) * (KPAD * 2) + (kb + 2 * t) * 2;
                    afrag[mt][0] = *reinterpret_cast<const uint32_t*>(q0);
                    afrag[mt][1] = *reinterpret_cast<const uint32_t*>(q1);
                    afrag[mt][2] = *reinterpret_cast<const uint32_t*>(q0 + 16);
                    afrag[mt][3] = *reinterpret_cast<const uint32_t*>(q1 + 16);
                }
                uint32_t bfrag[NT][2];
                #pragma unroll
                for (int nt = 0; nt < NT; nt++) {
                    const int n = wn * (BN / 2) + nt * 8 + g;
                    const char* q = pB + n * (KPAD * 2) + (kb + 2 * t) * 2;
                    bfrag[nt][0] = *reinterpret_cast<const uint32_t*>(q);
                    bfrag[nt][1] = *reinterpret_cast<const uint32_t*>(q + 16);
                }
                #pragma unroll
                for (int mt = 0; mt < 2; mt++)
                    #pragma unroll
                    for (int nt = 0; nt < NT; nt++)
                        mma16816(acc[mt][nt], afrag[mt], bfrag[nt]);
            }
        }
        __syncthreads();   // buf free for reuse by issue(ch+2)
    }

    // ---- epilogue: store C + fused partial alpha dots ----
    float sa[4] = {0.f, 0.f, 0.f, 0.f};   // rows: wm*32 + {0,8,16,24} + g
    float da[4] = {0.f, 0.f, 0.f, 0.f};
    #pragma unroll
    for (int mt = 0; mt < 2; mt++) {
        const int r0 = m0 + wm * 32 + mt * 16 + g;
        #pragma unroll
        for (int nt = 0; nt < NT; nt++) {
            const int col = n0 + wn * (BN / 2) + nt * 8 + 2 * t;
            const float v0 = avs[col], v1 = avs[col + 1];
            const float u0 = avd[col], u1 = avd[col + 1];
            sa[2 * mt]     += acc[mt][nt][0] * v0 + acc[mt][nt][1] * v1;
            da[2 * mt]     += acc[mt][nt][0] * u0 + acc[mt][nt][1] * u1;
            sa[2 * mt + 1] += acc[mt][nt][2] * v0 + acc[mt][nt][3] * v1;
            da[2 * mt + 1] += acc[mt][nt][2] * u0 + acc[mt][nt][3] * u1;
            if (r0 < M)
                *reinterpret_cast<float2*>(&C[(size_t)r0 * NC + col]) =
                    make_float2(acc[mt][nt][0], acc[mt][nt][1]);
            if (r0 + 8 < M)
                *reinterpret_cast<float2*>(&C[(size_t)(r0 + 8) * NC + col]) =
                    make_float2(acc[mt][nt][2], acc[mt][nt][3]);
        }
    }
    #pragma unroll
    for (int q = 0; q < 4; q++) {
        sa[q] += __shfl_xor_sync(0xffffffffu, sa[q], 1);
        sa[q] += __shfl_xor_sync(0xffffffffu, sa[q], 2);
        da[q] += __shfl_xor_sync(0xffffffffu, da[q], 1);
        da[q] += __shfl_xor_sync(0xffffffffu, da[q], 2);
    }
    if (t == 0) {
        #pragma unroll
        for (int q = 0; q < 4; q++) {
            const int r = m0 + wm * 32 + q * 8 + g;
            if (r < M) {
                atomicAdd(&as_out[r], sa[q]);
                atomicAdd(&ad_out[r], da[q]);
            }
        }
    }
}

// ---------------- fused softmax + aggregation: one block per dst ----------------
// No max-subtraction: logits ~ N(0, sqrt(2)); exp is overflow-safe here and the
// softmax ratio is mathematically identical.
template <int C, bool BF16OUT>
__global__ void aggregate_kernel(const float* __restrict__ h,
                                 const float* __restrict__ bias,
                                 const float* __restrict__ as_in,
                                 const float* __restrict__ ad_in,
                                 float* __restrict__ out) {
    __shared__ float ws[C];
    __shared__ int   ss[C];
    const int d   = blockIdx.x;
    const int tid = threadIdx.x;

    pdl_trigger();
    // PDL prologue: CSR data (g_off/g_srcs) is guaranteed by the event edge,
    // not by the immediately preceding kernel, so stage it before pdl_wait.
    const int beg = g_off[d];
    const int end = g_off[d + 1];
    float ad = 0.0f;
    bool waited = false;

    float a0 = 0.f, a1 = 0.f, a2 = 0.f, a3 = 0.f;
    float den = 0.0f;
    for (int cbeg = beg; cbeg < end; cbeg += C) {
        const int nchunk = min(C, end - cbeg);
        __syncthreads();
        int s = -1;
        if (tid < nchunk) {
            s = g_srcs[cbeg + tid];
            ss[tid] = s;
        }
        if (!waited) {           // first iteration: wait for h / as / ad producers
            pdl_wait();
            ad = ad_in[d];
            waited = true;
        }
        if (tid < nchunk) {
            float tt = as_in[s] + ad;
            float l = tt > 0.0f ? tt : NEG_SLOPE * tt;
            ws[tid] = __expf(l);
        }
        __syncthreads();
        int jj = 0;
        for (; jj + 4 <= nchunk; jj += 4) {
            float w0 = ws[jj],     w1 = ws[jj + 1];
            float w2 = ws[jj + 2], w3 = ws[jj + 3];
            den += (w0 + w1) + (w2 + w3);
            a0 += w0 * h[(size_t)ss[jj]     * C + tid];
            a1 += w1 * h[(size_t)ss[jj + 1] * C + tid];
            a2 += w2 * h[(size_t)ss[jj + 2] * C + tid];
            a3 += w3 * h[(size_t)ss[jj + 3] * C + tid];
        }
        for (; jj < nchunk; jj++) {
            float wt = ws[jj];
            den += wt;
            a0 += wt * h[(size_t)ss[jj] * C + tid];
        }
    }

    float acc = (a0 + a1) + (a2 + a3);
    float r = acc / den + bias[tid];
    if (BF16OUT) {
        r = fmaxf(r, 0.0f);
        __nv_bfloat16 hi, lo;
        bf16_split(r, hi, lo);
        g_thi[(size_t)d * C + tid] = hi;
        g_tlo[(size_t)d * C + tid] = lo;
    } else {
        out[(size_t)d * C + tid] = r;
    }
}

// ---------------- launch ----------------
extern "C" void kernel_launch(void* const* d_in, const int* in_sizes, int n_in,
                              void* d_out, int out_size) {
    const float* x   = (const float*)d_in[0];
    const void*  ei  = (const void*)d_in[1];
    const float* W1  = (const float*)d_in[2];
    const float* as1 = (const float*)d_in[3];
    const float* ad1 = (const float*)d_in[4];
    const float* b1  = (const float*)d_in[5];
    const float* W2  = (const float*)d_in[6];
    const float* as2 = (const float*)d_in[7];
    const float* ad2 = (const float*)d_in[8];
    const float* b2  = (const float*)d_in[9];
    float* out = (float*)d_out;

    float *g_h_p, *pas1, *pad1, *pas2, *pad2;
    cudaGetSymbolAddress((void**)&g_h_p, g_h);
    cudaGetSymbolAddress((void**)&pas1, g_as1);
    cudaGetSymbolAddress((void**)&pad1, g_ad1);
    cudaGetSymbolAddress((void**)&pas2, g_as2);
    cudaGetSymbolAddress((void**)&pad2, g_ad2);
    __nv_bfloat16 *xhi, *xlo, *thi, *tlo, *w1hi, *w1lo, *w2hi, *w2lo;
    cudaGetSymbolAddress((void**)&xhi, g_xhi);   cudaGetSymbolAddress((void**)&xlo, g_xlo);
    cudaGetSymbolAddress((void**)&thi, g_thi);   cudaGetSymbolAddress((void**)&tlo, g_tlo);
    cudaGetSymbolAddress((void**)&w1hi, g_w1hi); cudaGetSymbolAddress((void**)&w1lo, g_w1lo);
    cudaGetSymbolAddress((void**)&w2hi, g_w2hi); cudaGetSymbolAddress((void**)&w2lo, g_w2lo);

    constexpr int SMEM1 = 2 * (2 * ABYTES + 2 * (128 * KPAD * 2));   // 81920
    constexpr int SMEM2 = 2 * (2 * ABYTES + 2 * (64 * KPAD * 2));    // 61440

    // one-time host objects (no device memory involved)
    static cudaStream_t sCSR = nullptr, sConv = nullptr;
    static cudaEvent_t evFork = nullptr, evConv = nullptr, evCSR = nullptr;
    if (sCSR == nullptr) {
        cudaFuncSetAttribute(gemm_mma_kernel<CHID, 128>,
                             cudaFuncAttributeMaxDynamicSharedMemorySize, SMEM1);
        cudaFuncSetAttribute(gemm_mma_kernel<COUT, 64>,
                             cudaFuncAttributeMaxDynamicSharedMemorySize, SMEM2);
        cudaStreamCreateWithFlags(&sCSR, cudaStreamNonBlocking);
        cudaStreamCreateWithFlags(&sConv, cudaStreamNonBlocking);
        cudaEventCreateWithFlags(&evFork, cudaEventDisableTiming);
        cudaEventCreateWithFlags(&evConv, cudaEventDisableTiming);
        cudaEventCreateWithFlags(&evCSR, cudaEventDisableTiming);
    }

    const int TPB = 256;
    const int nblk_edges = (ETOT + TPB - 1) / TPB;
    const int MTILES = (NNODES + 127) / 128;   // 157
    const int CONV_ELEMS = NNODES * CIN + CIN * CHID + CHID * COUT;

    // PDL launch config (used on agg1->gemm2 and gemm2->agg2 adjacencies)
    cudaLaunchAttribute pdlAttr[1];
    pdlAttr[0].id = cudaLaunchAttributeProgrammaticStreamSerialization;
    pdlAttr[0].val.programmaticStreamSerializationAllowed = 1;

    // ---- stream 0: detect/init; fork point for BOTH side streams ----
    detect_init_kernel<<<NBLK_N, TPB>>>(ei);
    cudaEventRecord(evFork, 0);

    // ---- conversion branch (sConv) — legally forked from capture stream ----
    cudaStreamWaitEvent(sConv, evFork, 0);
    conv_all_kernel<<<(CONV_ELEMS + TPB - 1) / TPB, TPB, 0, sConv>>>(x, W1, W2);
    cudaEventRecord(evConv, sConv);

    // ---- CSR branch (sCSR) ----
    cudaStreamWaitEvent(sCSR, evFork, 0);
    convert_count_kernel<<<nblk_edges, TPB, 0, sCSR>>>(ei);
    scan_part_kernel<<<NBLK_N, 256, 0, sCSR>>>();
    scan_write_kernel<<<NBLK_N, 256, 0, sCSR>>>();
    fill_kernel<<<nblk_edges, TPB, 0, sCSR>>>();
    cudaEventRecord(evCSR, sCSR);

    // ---- main: GEMM1 (needs conv output + detect/init zeros) ----
    cudaStreamWaitEvent(0, evConv, 0);
    {
        dim3 grid(CHID / 128, MTILES);
        gemm_mma_kernel<CHID, 128><<<grid, 256, SMEM1>>>(
            xhi, xlo, w1hi, w1lo, g_h_p, as1, ad1, pas1, pad1, NNODES, CIN);
    }

    // ---- join CSR, aggregate1 ----
    cudaStreamWaitEvent(0, evCSR, 0);
    aggregate_kernel<CHID, true><<<NNODES, CHID>>>(g_h_p, b1, pas1, pad1, nullptr);

    // ---- layer 2 (PDL chained: agg1 -> gemm2 -> agg2) ----
    {
        cudaLaunchConfig_t cfg = {};
        cfg.gridDim = dim3(COUT / 64, MTILES);
        cfg.blockDim = dim3(256, 1, 1);
        cfg.dynamicSmemBytes = SMEM2;
        cfg.stream = 0;
        cfg.attrs = pdlAttr;
        cfg.numAttrs = 1;
        int M = NNODES, K = CHID;
        cudaLaunchKernelEx(&cfg, gemm_mma_kernel<COUT, 64>,
                           (const __nv_bfloat16*)thi, (const __nv_bfloat16*)tlo,
                           (const __nv_bfloat16*)w2hi, (const __nv_bfloat16*)w2lo,
                           (float*)g_h_p, (const float*)as2, (const float*)ad2,
                           (float*)pas2, (float*)pad2, M, K);
    }
    {
        cudaLaunchConfig_t cfg = {};
        cfg.gridDim = dim3(NNODES, 1, 1);
        cfg.blockDim = dim3(COUT, 1, 1);
        cfg.dynamicSmemBytes = 0;
        cfg.stream = 0;
        cfg.attrs = pdlAttr;
        cfg.numAttrs = 1;
        cudaLaunchKernelEx(&cfg, aggregate_kernel<COUT, false>,
                           (const float*)g_h_p, (const float*)b2,
                           (const float*)pas2, (const float*)pad2, (float*)out);
    }
}

// round 12
// speedup vs baseline: 1.0375x; 1.0375x over previous
#include <cuda_runtime.h>
#include <cuda_bf16.h>
#include <math_constants.h>
#include <cstdint>

// ---------------- problem constants ----------------
#define NNODES 20000
#define NEDGES 320000
#define ETOT   (NEDGES + NNODES)   // + self loops
#define CIN    256
#define CHID   256
#define COUT   128
#define NEG_SLOPE 0.2f
#define NBLK_N ((NNODES + 255) / 256)   // 79

// ---------------- device scratch (no allocations allowed) ----------------
__device__ float g_h[NNODES * CHID];     // GEMM output of current layer
__device__ float g_as1[NNODES];
__device__ float g_ad1[NNODES];
__device__ float g_as2[NNODES];
__device__ float g_ad2[NNODES];
__device__ int   g_deg[NNODES];
__device__ int   g_bsum[NBLK_N];
__device__ int   g_off[NNODES + 1];
__device__ int   g_cur[NNODES];
__device__ int   g_srcs[ETOT];
__device__ int   g_esrc[ETOT];
__device__ int   g_edst[ETOT];
__device__ int   g_is64;

// bf16 split operands (weights + layer-2 activations; x converts inside GEMM1)
__device__ __nv_bfloat16 g_thi[NNODES * CHID];   // layer-2 input (written by aggregate1)
__device__ __nv_bfloat16 g_tlo[NNODES * CHID];
__device__ __nv_bfloat16 g_w1hi[CHID * CIN];     // W1^T : [N=CHID][K=CIN]
__device__ __nv_bfloat16 g_w1lo[CHID * CIN];
__device__ __nv_bfloat16 g_w2hi[COUT * CHID];    // W2^T : [N=COUT][K=CHID]
__device__ __nv_bfloat16 g_w2lo[COUT * CHID];

// ---------------- PDL helpers (no-ops when not PDL-launched) ----------------
__device__ __forceinline__ void pdl_trigger() {
    asm volatile("griddepcontrol.launch_dependents;" ::: "memory");
}
__device__ __forceinline__ void pdl_wait() {
    asm volatile("griddepcontrol.wait;" ::: "memory");
}

// ---------------- split helpers ----------------
__device__ __forceinline__ void bf16_split(float v, __nv_bfloat16& hi, __nv_bfloat16& lo) {
    hi = __float2bfloat16(v);
    lo = __float2bfloat16(v - __bfloat162float(hi));
}
__device__ __forceinline__ void split_pair(float v0, float v1,
                                           uint32_t& hw, uint32_t& lw) {
    __nv_bfloat16 h0, l0, h1, l1;
    bf16_split(v0, h0, l0);
    bf16_split(v1, h1, l1);
    hw = ((uint32_t)__bfloat16_as_ushort(h1) << 16) | __bfloat16_as_ushort(h0);
    lw = ((uint32_t)__bfloat16_as_ushort(l1) << 16) | __bfloat16_as_ushort(l0);
}

// ---------------- detect dtype + zero init (merged) ----------------
__global__ void detect_init_kernel(const void* __restrict__ ei) {
    int i = blockIdx.x * blockDim.x + threadIdx.x;
    if (i < NNODES) {
        g_deg[i] = 0;
        g_as1[i] = 0.f; g_ad1[i] = 0.f;
        g_as2[i] = 0.f; g_ad2[i] = 0.f;
    }
    if (blockIdx.x == 0) {
        const long long* p = (const long long*)ei;
        int bad = 0;
        #pragma unroll
        for (int k = threadIdx.x; k < 2048; k += 256) {
            long long v = p[k];
            if (v < 0 || v >= NNODES) bad = 1;
        }
        int anybad = __syncthreads_or(bad);
        if (threadIdx.x == 0) g_is64 = !anybad;
    }
}

// ---------------- convert W1 + W2 to bf16 hi/lo (weights only, tiny) ----------------
__global__ void conv_w_kernel(const float* __restrict__ W1,
                              const float* __restrict__ W2) {
    int i = blockIdx.x * blockDim.x + threadIdx.x;
    if (i < CIN * CHID) {
        int k = i / CHID, n = i % CHID;           // W1[k][n] -> w1t[n][k]
        bf16_split(W1[i], g_w1hi[n * CIN + k], g_w1lo[n * CIN + k]);
        return;
    }
    i -= CIN * CHID;
    if (i < CHID * COUT) {
        int k = i / COUT, n = i % COUT;           // W2[k][n] -> w2t[n][k]
        bf16_split(W2[i], g_w2hi[n * CHID + k], g_w2lo[n * CHID + k]);
    }
}

// ---------------- convert + degree count ----------------
__global__ void convert_count_kernel(const void* __restrict__ ei) {
    int e = blockIdx.x * blockDim.x + threadIdx.x;
    if (e >= ETOT) return;
    int s, d;
    if (e < NEDGES) {
        if (g_is64) {
            const long long* p = (const long long*)ei;
            s = (int)p[e]; d = (int)p[NEDGES + e];
        } else {
            const int* p = (const int*)ei;
            s = p[e]; d = p[NEDGES + e];
        }
    } else {
        s = e - NEDGES; d = s;
    }
    g_esrc[e] = s;
    g_edst[e] = d;
    atomicAdd(&g_deg[d], 1);
}

// ---------------- multi-block scan ----------------
__global__ void scan_part_kernel() {
    __shared__ int sh[256];
    int i = blockIdx.x * 256 + threadIdx.x;
    sh[threadIdx.x] = (i < NNODES) ? g_deg[i] : 0;
    __syncthreads();
    #pragma unroll
    for (int st = 128; st > 0; st >>= 1) {
        if (threadIdx.x < st) sh[threadIdx.x] += sh[threadIdx.x + st];
        __syncthreads();
    }
    if (threadIdx.x == 0) g_bsum[blockIdx.x] = sh[0];
}

__global__ void scan_write_kernel() {
    __shared__ int sh[256];
    __shared__ int base_sh;
    const int t = threadIdx.x;
    const int b = blockIdx.x;
    int pv = (t < b && t < NBLK_N) ? g_bsum[t] : 0;
    sh[t] = pv;
    __syncthreads();
    #pragma unroll
    for (int st = 128; st > 0; st >>= 1) {
        if (t < st) sh[t] += sh[t + st];
        __syncthreads();
    }
    if (t == 0) base_sh = sh[0];
    __syncthreads();
    const int base = base_sh;
    __syncthreads();
    int i = b * 256 + t;
    int d = (i < NNODES) ? g_deg[i] : 0;
    sh[t] = d;
    __syncthreads();
    #pragma unroll
    for (int st = 1; st < 256; st <<= 1) {
        int v = (t >= st) ? sh[t - st] : 0;
        __syncthreads();
        sh[t] += v;
        __syncthreads();
    }
    if (i < NNODES) {
        int off = base + sh[t] - d;
        g_off[i] = off;
        g_cur[i] = off;
    }
    if (b == NBLK_N - 1 && t == 255) g_off[NNODES] = base + sh[255];
}

__global__ void fill_kernel() {
    int e = blockIdx.x * blockDim.x + threadIdx.x;
    if (e >= ETOT) return;
    int pos = atomicAdd(&g_cur[g_edst[e]], 1);
    g_srcs[pos] = g_esrc[e];
}

// ---------------- bf16-split warp MMA GEMM ----------------
// C[M x NC] = (Ahi+Alo)[M x K] @ ((Bhi+Blo)[NC x K])^T, 3 combos, fp32 accum.
// CTA tile 128 x BN, 8 warps (4 m x 2 n), warp tile 32 x BN/2, mma m16n8k16.
// AFP32: A arrives as fp32 and is split to bf16 hi/lo in-register (fused conv).
// Fused epilogue: atomicAdd partial alpha_src/alpha_dst dots per row.
#define KC    32
#define KPAD  40                          // 80B row stride, conflict-free fragments
#define ABYTES (128 * KPAD * 2)           // 10240

__device__ __forceinline__ void mma16816(float* c, const uint32_t* a, const uint32_t* b) {
    asm volatile(
        "mma.sync.aligned.m16n8k16.row.col.f32.bf16.bf16.f32 "
        "{%0,%1,%2,%3}, {%4,%5,%6,%7}, {%8,%9}, {%0,%1,%2,%3};"
        : "+f"(c[0]), "+f"(c[1]), "+f"(c[2]), "+f"(c[3])
        : "r"(a[0]), "r"(a[1]), "r"(a[2]), "r"(a[3]), "r"(b[0]), "r"(b[1]));
}

__device__ __forceinline__ uint32_t smem_u32(const void* p) {
    uint32_t a;
    asm("{ .reg .u64 t; cvta.to.shared.u64 t, %1; cvt.u32.u64 %0, t; }" : "=r"(a) : "l"(p));
    return a;
}
__device__ __forceinline__ void cp16(uint32_t dst, const void* src) {
    asm volatile("cp.async.cg.shared.global [%0], [%1], 16;" :: "r"(dst), "l"(src));
}

template <int NC, int BN, bool AFP32>
__global__ __launch_bounds__(256)
void gemm_mma_kernel(const void* __restrict__ Aarg, const __nv_bfloat16* __restrict__ Alo,
                     const __nv_bfloat16* __restrict__ Bhi, const __nv_bfloat16* __restrict__ Blo,
                     float* __restrict__ C,
                     const float* __restrict__ avs, const float* __restrict__ avd,
                     float* __restrict__ as_out, float* __restrict__ ad_out,
                     int M, int K) {
    constexpr int NT      = BN / 16;            // n-tiles per warp
    constexpr int BBYTES  = BN * KPAD * 2;
    constexpr int BUFB    = 2 * ABYTES + 2 * BBYTES;

    extern __shared__ char smem[];
    const uint32_t sb = smem_u32(smem);

    const int tid   = threadIdx.x;
    const int wid   = tid >> 5;
    const int lane  = tid & 31;
    const int wm    = wid & 3;
    const int wn    = wid >> 2;
    const int g     = lane >> 2;
    const int t     = lane & 3;
    const int m0    = blockIdx.y * 128;
    const int n0    = blockIdx.x * BN;

    const float* Af = (const float*)Aarg;
    const __nv_bfloat16* Ahi = (const __nv_bfloat16*)Aarg;

    pdl_trigger();          // let dependent kernel launch early
    pdl_wait();             // inputs may come from the immediately preceding kernel

    float acc[2][NT][4];
    #pragma unroll
    for (int i = 0; i < 2; i++)
        #pragma unroll
        for (int j = 0; j < NT; j++)
            #pragma unroll
            for (int q = 0; q < 4; q++) acc[i][j][q] = 0.0f;

    const int NCHUNK = K / KC;

    // fused-conversion A staging (AFP32): one thread = 16 contiguous fp32
    const int arowA = min(m0 + (tid >> 1), M - 1);
    const int halfA = tid & 1;
    float areg[AFP32 ? 16 : 1];

    auto ldgA = [&](int ch) {
        if constexpr (AFP32) {
            const float* p = Af + (size_t)arowA * K + ch * KC + halfA * 16;
            #pragma unroll
            for (int v = 0; v < 4; v++)
                *reinterpret_cast<float4*>(&areg[4 * v]) =
                    *reinterpret_cast<const float4*>(p + 4 * v);
        }
    };
    auto stsA = [&](int buf) {
        if constexpr (AFP32) {
            uint32_t hw[8], lw[8];
            #pragma unroll
            for (int i = 0; i < 8; i++)
                split_pair(areg[2 * i], areg[2 * i + 1], hw[i], lw[i]);
            char* base = smem + buf * BUFB + (tid >> 1) * (KPAD * 2) + halfA * 32;
            *reinterpret_cast<uint4*>(base)      = make_uint4(hw[0], hw[1], hw[2], hw[3]);
            *reinterpret_cast<uint4*>(base + 16) = make_uint4(hw[4], hw[5], hw[6], hw[7]);
            char* lbase = base + ABYTES;
            *reinterpret_cast<uint4*>(lbase)      = make_uint4(lw[0], lw[1], lw[2], lw[3]);
            *reinterpret_cast<uint4*>(lbase + 16) = make_uint4(lw[4], lw[5], lw[6], lw[7]);
        }
    };

    auto issue_chunk = [&](int ch, int buf) {
        const int kc0 = ch * KC;
        const uint32_t bbase = sb + buf * BUFB;
        if constexpr (!AFP32) {
            #pragma unroll
            for (int it = 0; it < 2; it++) {                // A: 128 rows x 4 slots
                const int idx = tid + it * 256;
                const int row = idx >> 2;
                const int c4  = idx & 3;
                const int arow = min(m0 + row, M - 1);      // clamp; garbage rows unsaved
                const size_t ao = (size_t)arow * K + kc0 + c4 * 8;
                const uint32_t so = (uint32_t)(row * (KPAD * 2) + c4 * 16);
                cp16(bbase + so, Ahi + ao);
                cp16(bbase + ABYTES + so, Alo + ao);
            }
        }
        #pragma unroll
        for (int it = 0; it < BN * 4 / 256; it++) {         // B: BN rows x 4 slots
            const int idx = tid + it * 256;
            const int row = idx >> 2;
            const int c4  = idx & 3;
            const size_t bo = (size_t)(n0 + row) * K + kc0 + c4 * 8;  // NC mult of BN
            const uint32_t so = (uint32_t)(row * (KPAD * 2) + c4 * 16);
            cp16(bbase + 2 * ABYTES + so, Bhi + bo);
            cp16(bbase + 2 * ABYTES + BBYTES + so, Blo + bo);
        }
        asm volatile("cp.async.commit_group;" ::: "memory");
    };

    // prologue
    ldgA(0);
    issue_chunk(0, 0);
    stsA(0);

    for (int ch = 0; ch < NCHUNK; ch++) {
        const int buf = ch & 1;
        const bool more = (ch + 1 < NCHUNK);
        if (more) {
            ldgA(ch + 1);
            issue_chunk(ch + 1, buf ^ 1);
        }
        if (more) asm volatile("cp.async.wait_group 1;" ::: "memory");
        else      asm volatile("cp.async.wait_group 0;" ::: "memory");
        __syncthreads();

        const char* pbuf = smem + buf * BUFB;
        #pragma unroll
        for (int ks = 0; ks < KC / 16; ks++) {
            const int kb = ks * 16;
            #pragma unroll
            for (int combo = 0; combo < 3; combo++) {
                const char* pA = pbuf + ((combo == 2) ? ABYTES : 0);
                const char* pB = pbuf + 2 * ABYTES + ((combo == 1) ? BBYTES : 0);

                uint32_t afrag[2][4];
                #pragma unroll
                for (int mt = 0; mt < 2; mt++) {
                    const int r0 = wm * 32 + mt * 16 + g;
                    const char* q0 = pA + r0 * (KPAD * 2) + (kb + 2 * t) * 2;
                    const char* q1 = pA + (r0 + 8) * (KPAD * 2) + (kb + 2 * t) * 2;
                    afrag[mt][0] = *reinterpret_cast<const uint32_t*>(q0);
                    afrag[mt][1] = *reinterpret_cast<const uint32_t*>(q1);
                    afrag[mt][2] = *reinterpret_cast<const uint32_t*>(q0 + 16);
                    afrag[mt][3] = *reinterpret_cast<const uint32_t*>(q1 + 16);
                }
                uint32_t bfrag[NT][2];
                #pragma unroll
                for (int nt = 0; nt < NT; nt++) {
                    const int n = wn * (BN / 2) + nt * 8 + g;
                    const char* q = pB + n * (KPAD * 2) + (kb + 2 * t) * 2;
                    bfrag[nt][0] = *reinterpret_cast<const uint32_t*>(q);
                    bfrag[nt][1] = *reinterpret_cast<const uint32_t*>(q + 16);
                }
                #pragma unroll
                for (int mt = 0; mt < 2; mt++)
                    #pragma unroll
                    for (int nt = 0; nt < NT; nt++)
                        mma16816(acc[mt][nt], afrag[mt], bfrag[nt]);
            }
        }
        if (more) stsA(buf ^ 1);   // visible after next iteration's __syncthreads
        __syncthreads();           // buf free for reuse
    }

    // ---- epilogue: store C + fused partial alpha dots ----
    float sa[4] = {0.f, 0.f, 0.f, 0.f};   // rows: wm*32 + {0,8,16,24} + g
    float da[4] = {0.f, 0.f, 0.f, 0.f};
    #pragma unroll
    for (int mt = 0; mt < 2; mt++) {
        const int r0 = m0 + wm * 32 + mt * 16 + g;
        #pragma unroll
        for (int nt = 0; nt < NT; nt++) {
            const int col = n0 + wn * (BN / 2) + nt * 8 + 2 * t;
            const float v0 = avs[col], v1 = avs[col + 1];
            const float u0 = avd[col], u1 = avd[col + 1];
            sa[2 * mt]     += acc[mt][nt][0] * v0 + acc[mt][nt][1] * v1;
            da[2 * mt]     += acc[mt][nt][0] * u0 + acc[mt][nt][1] * u1;
            sa[2 * mt + 1] += acc[mt][nt][2] * v0 + acc[mt][nt][3] * v1;
            da[2 * mt + 1] += acc[mt][nt][2] * u0 + acc[mt][nt][3] * u1;
            if (r0 < M)
                *reinterpret_cast<float2*>(&C[(size_t)r0 * NC + col]) =
                    make_float2(acc[mt][nt][0], acc[mt][nt][1]);
            if (r0 + 8 < M)
                *reinterpret_cast<float2*>(&C[(size_t)(r0 + 8) * NC + col]) =
                    make_float2(acc[mt][nt][2], acc[mt][nt][3]);
        }
    }
    #pragma unroll
    for (int q = 0; q < 4; q++) {
        sa[q] += __shfl_xor_sync(0xffffffffu, sa[q], 1);
        sa[q] += __shfl_xor_sync(0xffffffffu, sa[q], 2);
        da[q] += __shfl_xor_sync(0xffffffffu, da[q], 1);
        da[q] += __shfl_xor_sync(0xffffffffu, da[q], 2);
    }
    if (t == 0) {
        #pragma unroll
        for (int q = 0; q < 4; q++) {
            const int r = m0 + wm * 32 + q * 8 + g;
            if (r < M) {
                atomicAdd(&as_out[r], sa[q]);
                atomicAdd(&ad_out[r], da[q]);
            }
        }
    }
}

// ---------------- fused softmax + aggregation: one block per dst ----------------
// No max-subtraction: logits ~ N(0, sqrt(2)); exp is overflow-safe here and the
// softmax ratio is mathematically identical.
template <int C, bool BF16OUT>
__global__ void aggregate_kernel(const float* __restrict__ h,
                                 const float* __restrict__ bias,
                                 const float* __restrict__ as_in,
                                 const float* __restrict__ ad_in,
                                 float* __restrict__ out) {
    __shared__ float ws[C];
    __shared__ int   ss[C];
    const int d   = blockIdx.x;
    const int tid = threadIdx.x;

    pdl_trigger();
    // PDL prologue: CSR data (g_off/g_srcs) is guaranteed by the event edge,
    // not by the immediately preceding kernel, so stage it before pdl_wait.
    const int beg = g_off[d];
    const int end = g_off[d + 1];
    float ad = 0.0f;
    bool waited = false;

    float a0 = 0.f, a1 = 0.f, a2 = 0.f, a3 = 0.f;
    float den = 0.0f;
    for (int cbeg = beg; cbeg < end; cbeg += C) {
        const int nchunk = min(C, end - cbeg);
        __syncthreads();
        int s = -1;
        if (tid < nchunk) {
            s = g_srcs[cbeg + tid];
            ss[tid] = s;
        }
        if (!waited) {           // first iteration: wait for h / as / ad producers
            pdl_wait();
            ad = ad_in[d];
            waited = true;
        }
        if (tid < nchunk) {
            float tt = as_in[s] + ad;
            float l = tt > 0.0f ? tt : NEG_SLOPE * tt;
            ws[tid] = __expf(l);
        }
        __syncthreads();
        int jj = 0;
        for (; jj + 4 <= nchunk; jj += 4) {
            float w0 = ws[jj],     w1 = ws[jj + 1];
            float w2 = ws[jj + 2], w3 = ws[jj + 3];
            den += (w0 + w1) + (w2 + w3);
            a0 += w0 * h[(size_t)ss[jj]     * C + tid];
            a1 += w1 * h[(size_t)ss[jj + 1] * C + tid];
            a2 += w2 * h[(size_t)ss[jj + 2] * C + tid];
            a3 += w3 * h[(size_t)ss[jj + 3] * C + tid];
        }
        for (; jj < nchunk; jj++) {
            float wt = ws[jj];
            den += wt;
            a0 += wt * h[(size_t)ss[jj] * C + tid];
        }
    }

    float acc = (a0 + a1) + (a2 + a3);
    float r = acc / den + bias[tid];
    if (BF16OUT) {
        r = fmaxf(r, 0.0f);
        __nv_bfloat16 hi, lo;
        bf16_split(r, hi, lo);
        g_thi[(size_t)d * C + tid] = hi;
        g_tlo[(size_t)d * C + tid] = lo;
    } else {
        out[(size_t)d * C + tid] = r;
    }
}

// ---------------- launch ----------------
extern "C" void kernel_launch(void* const* d_in, const int* in_sizes, int n_in,
                              void* d_out, int out_size) {
    const float* x   = (const float*)d_in[0];
    const void*  ei  = (const void*)d_in[1];
    const float* W1  = (const float*)d_in[2];
    const float* as1 = (const float*)d_in[3];
    const float* ad1 = (const float*)d_in[4];
    const float* b1  = (const float*)d_in[5];
    const float* W2  = (const float*)d_in[6];
    const float* as2 = (const float*)d_in[7];
    const float* ad2 = (const float*)d_in[8];
    const float* b2  = (const float*)d_in[9];
    float* out = (float*)d_out;

    float *g_h_p, *pas1, *pad1, *pas2, *pad2;
    cudaGetSymbolAddress((void**)&g_h_p, g_h);
    cudaGetSymbolAddress((void**)&pas1, g_as1);
    cudaGetSymbolAddress((void**)&pad1, g_ad1);
    cudaGetSymbolAddress((void**)&pas2, g_as2);
    cudaGetSymbolAddress((void**)&pad2, g_ad2);
    __nv_bfloat16 *thi, *tlo, *w1hi, *w1lo, *w2hi, *w2lo;
    cudaGetSymbolAddress((void**)&thi, g_thi);   cudaGetSymbolAddress((void**)&tlo, g_tlo);
    cudaGetSymbolAddress((void**)&w1hi, g_w1hi); cudaGetSymbolAddress((void**)&w1lo, g_w1lo);
    cudaGetSymbolAddress((void**)&w2hi, g_w2hi); cudaGetSymbolAddress((void**)&w2lo, g_w2lo);

    constexpr int SMEM64 = 2 * (2 * ABYTES + 2 * (64 * KPAD * 2));   // 61440

    // one-time host objects (no device memory involved)
    static cudaStream_t sCSR = nullptr, sConv = nullptr;
    static cudaEvent_t evFork = nullptr, evConv = nullptr, evCSR = nullptr;
    if (sCSR == nullptr) {
        cudaFuncSetAttribute(gemm_mma_kernel<CHID, 64, true>,
                             cudaFuncAttributeMaxDynamicSharedMemorySize, SMEM64);
        cudaFuncSetAttribute(gemm_mma_kernel<COUT, 64, false>,
                             cudaFuncAttributeMaxDynamicSharedMemorySize, SMEM64);
        cudaStreamCreateWithFlags(&sCSR, cudaStreamNonBlocking);
        cudaStreamCreateWithFlags(&sConv, cudaStreamNonBlocking);
        cudaEventCreateWithFlags(&evFork, cudaEventDisableTiming);
        cudaEventCreateWithFlags(&evConv, cudaEventDisableTiming);
        cudaEventCreateWithFlags(&evCSR, cudaEventDisableTiming);
    }

    const int TPB = 256;
    const int nblk_edges = (ETOT + TPB - 1) / TPB;
    const int MTILES = (NNODES + 127) / 128;   // 157
    const int CONVW_ELEMS = CIN * CHID + CHID * COUT;

    // PDL launch config (used on agg1->gemm2 and gemm2->agg2 adjacencies)
    cudaLaunchAttribute pdlAttr[1];
    pdlAttr[0].id = cudaLaunchAttributeProgrammaticStreamSerialization;
    pdlAttr[0].val.programmaticStreamSerializationAllowed = 1;

    // ---- stream 0: detect/init; fork point for BOTH side streams ----
    detect_init_kernel<<<NBLK_N, TPB>>>(ei);
    cudaEventRecord(evFork, 0);

    // ---- conversion branch (sConv): weights only ----
    cudaStreamWaitEvent(sConv, evFork, 0);
    conv_w_kernel<<<(CONVW_ELEMS + TPB - 1) / TPB, TPB, 0, sConv>>>(W1, W2);
    cudaEventRecord(evConv, sConv);

    // ---- CSR branch (sCSR) ----
    cudaStreamWaitEvent(sCSR, evFork, 0);
    convert_count_kernel<<<nblk_edges, TPB, 0, sCSR>>>(ei);
    scan_part_kernel<<<NBLK_N, 256, 0, sCSR>>>();
    scan_write_kernel<<<NBLK_N, 256, 0, sCSR>>>();
    fill_kernel<<<nblk_edges, TPB, 0, sCSR>>>();
    cudaEventRecord(evCSR, sCSR);

    // ---- main: GEMM1 (fp32 x, fused bf16 split; needs W conv + zeros) ----
    cudaStreamWaitEvent(0, evConv, 0);
    {
        dim3 grid(CHID / 64, MTILES);
        gemm_mma_kernel<CHID, 64, true><<<grid, 256, SMEM64>>>(
            (const void*)x, nullptr, w1hi, w1lo, g_h_p, as1, ad1, pas1, pad1,
            NNODES, CIN);
    }

    // ---- join CSR, aggregate1 ----
    cudaStreamWaitEvent(0, evCSR, 0);
    aggregate_kernel<CHID, true><<<NNODES, CHID>>>(g_h_p, b1, pas1, pad1, nullptr);

    // ---- layer 2 (PDL chained: agg1 -> gemm2 -> agg2) ----
    {
        cudaLaunchConfig_t cfg = {};
        cfg.gridDim = dim3(COUT / 64, MTILES);
        cfg.blockDim = dim3(256, 1, 1);
        cfg.dynamicSmemBytes = SMEM64;
        cfg.stream = 0;
        cfg.attrs = pdlAttr;
        cfg.numAttrs = 1;
        int M = NNODES, K = CHID;
        cudaLaunchKernelEx(&cfg, gemm_mma_kernel<COUT, 64, false>,
                           (const void*)thi, (const __nv_bfloat16*)tlo,
                           (const __nv_bfloat16*)w2hi, (const __nv_bfloat16*)w2lo,
                           (float*)g_h_p, (const float*)as2, (const float*)ad2,
                           (float*)pas2, (float*)pad2, M, K);
    }
    {
        cudaLaunchConfig_t cfg = {};
        cfg.gridDim = dim3(NNODES, 1, 1);
        cfg.blockDim = dim3(COUT, 1, 1);
        cfg.dynamicSmemBytes = 0;
        cfg.stream = 0;
        cfg.attrs = pdlAttr;
        cfg.numAttrs = 1;
        cudaLaunchKernelEx(&cfg, aggregate_kernel<COUT, false>,
                           (const float*)g_h_p, (const float*)b2,
                           (const float*)pas2, (const float*)pad2, (float*)out);
    }
}

// round 13
// speedup vs baseline: 1.3578x; 1.3086x over previous
#include <cuda_runtime.h>
#include <cuda_bf16.h>
#include <math_constants.h>
#include <cstdint>

// ---------------- problem constants ----------------
#define NNODES 20000
#define NEDGES 320000
#define ETOT   (NEDGES + NNODES)   // + self loops
#define CIN    256
#define CHID   256
#define COUT   128
#define NEG_SLOPE 0.2f
#define NBLK_N ((NNODES + 255) / 256)   // 79
#define CONVW_ELEMS (CIN * CHID + CHID * COUT)          // 98304
#define NBLK_W ((CONVW_ELEMS + 255) / 256)              // 384

// ---------------- device scratch (no allocations allowed) ----------------
__device__ float g_h[NNODES * CHID];     // GEMM output of current layer
__device__ float g_as1[NNODES];
__device__ float g_ad1[NNODES];
__device__ float g_as2[NNODES];
__device__ float g_ad2[NNODES];
__device__ int   g_deg[NNODES];
__device__ int   g_bsum[NBLK_N];
__device__ int   g_off[NNODES + 1];
__device__ int   g_cur[NNODES];
__device__ int   g_srcs[ETOT];
__device__ int   g_esrc[ETOT];
__device__ int   g_edst[ETOT];
__device__ int   g_is64;

// bf16 split operands (weights + layer-2 activations; x converts inside GEMM1)
__device__ __nv_bfloat16 g_thi[NNODES * CHID];   // layer-2 input (written by aggregate1)
__device__ __nv_bfloat16 g_tlo[NNODES * CHID];
__device__ __nv_bfloat16 g_w1hi[CHID * CIN];     // W1^T : [N=CHID][K=CIN]
__device__ __nv_bfloat16 g_w1lo[CHID * CIN];
__device__ __nv_bfloat16 g_w2hi[COUT * CHID];    // W2^T : [N=COUT][K=CHID]
__device__ __nv_bfloat16 g_w2lo[COUT * CHID];

// ---------------- PDL helpers (no-ops when not PDL-launched) ----------------
__device__ __forceinline__ void pdl_trigger() {
    asm volatile("griddepcontrol.launch_dependents;" ::: "memory");
}
__device__ __forceinline__ void pdl_wait() {
    asm volatile("griddepcontrol.wait;" ::: "memory");
}

// ---------------- split helpers ----------------
__device__ __forceinline__ void bf16_split(float v, __nv_bfloat16& hi, __nv_bfloat16& lo) {
    hi = __float2bfloat16(v);
    lo = __float2bfloat16(v - __bfloat162float(hi));
}
__device__ __forceinline__ void split_pair(float v0, float v1,
                                           uint32_t& hw, uint32_t& lw) {
    __nv_bfloat16 h0, l0, h1, l1;
    bf16_split(v0, h0, l0);
    bf16_split(v1, h1, l1);
    hw = ((uint32_t)__bfloat16_as_ushort(h1) << 16) | __bfloat16_as_ushort(h0);
    lw = ((uint32_t)__bfloat16_as_ushort(l1) << 16) | __bfloat16_as_ushort(l0);
}

// ---------------- setup: detect dtype + zero init + weight conversion ----------------
__global__ void setup_kernel(const void* __restrict__ ei,
                             const float* __restrict__ W1,
                             const float* __restrict__ W2) {
    const int b = blockIdx.x;
    if (b < NBLK_N) {
        int i = b * blockDim.x + threadIdx.x;
        if (i < NNODES) {
            g_deg[i] = 0;
            g_as1[i] = 0.f; g_ad1[i] = 0.f;
            g_as2[i] = 0.f; g_ad2[i] = 0.f;
        }
        if (b == 0) {
            const long long* p = (const long long*)ei;
            int bad = 0;
            #pragma unroll
            for (int k = threadIdx.x; k < 2048; k += 256) {
                long long v = p[k];
                if (v < 0 || v >= NNODES) bad = 1;
            }
            int anybad = __syncthreads_or(bad);
            if (threadIdx.x == 0) g_is64 = !anybad;
        }
    } else {
        int i = (b - NBLK_N) * blockDim.x + threadIdx.x;
        if (i < CIN * CHID) {
            int k = i / CHID, n = i % CHID;           // W1[k][n] -> w1t[n][k]
            bf16_split(W1[i], g_w1hi[n * CIN + k], g_w1lo[n * CIN + k]);
        } else if (i < CONVW_ELEMS) {
            int j = i - CIN * CHID;
            int k = j / COUT, n = j % COUT;           // W2[k][n] -> w2t[n][k]
            bf16_split(W2[j], g_w2hi[n * CHID + k], g_w2lo[n * CHID + k]);
        }
    }
}

// ---------------- convert + degree count ----------------
__global__ void convert_count_kernel(const void* __restrict__ ei) {
    int e = blockIdx.x * blockDim.x + threadIdx.x;
    if (e >= ETOT) return;
    int s, d;
    if (e < NEDGES) {
        if (g_is64) {
            const long long* p = (const long long*)ei;
            s = (int)p[e]; d = (int)p[NEDGES + e];
        } else {
            const int* p = (const int*)ei;
            s = p[e]; d = p[NEDGES + e];
        }
    } else {
        s = e - NEDGES; d = s;
    }
    g_esrc[e] = s;
    g_edst[e] = d;
    atomicAdd(&g_deg[d], 1);
}

// ---------------- multi-block scan ----------------
__global__ void scan_part_kernel() {
    __shared__ int sh[256];
    int i = blockIdx.x * 256 + threadIdx.x;
    sh[threadIdx.x] = (i < NNODES) ? g_deg[i] : 0;
    __syncthreads();
    #pragma unroll
    for (int st = 128; st > 0; st >>= 1) {
        if (threadIdx.x < st) sh[threadIdx.x] += sh[threadIdx.x + st];
        __syncthreads();
    }
    if (threadIdx.x == 0) g_bsum[blockIdx.x] = sh[0];
}

__global__ void scan_write_kernel() {
    __shared__ int sh[256];
    __shared__ int base_sh;
    const int t = threadIdx.x;
    const int b = blockIdx.x;
    int pv = (t < b && t < NBLK_N) ? g_bsum[t] : 0;
    sh[t] = pv;
    __syncthreads();
    #pragma unroll
    for (int st = 128; st > 0; st >>= 1) {
        if (t < st) sh[t] += sh[t + st];
        __syncthreads();
    }
    if (t == 0) base_sh = sh[0];
    __syncthreads();
    const int base = base_sh;
    __syncthreads();
    int i = b * 256 + t;
    int d = (i < NNODES) ? g_deg[i] : 0;
    sh[t] = d;
    __syncthreads();
    #pragma unroll
    for (int st = 1; st < 256; st <<= 1) {
        int v = (t >= st) ? sh[t - st] : 0;
        __syncthreads();
        sh[t] += v;
        __syncthreads();
    }
    if (i < NNODES) {
        int off = base + sh[t] - d;
        g_off[i] = off;
        g_cur[i] = off;
    }
    if (b == NBLK_N - 1 && t == 255) g_off[NNODES] = base + sh[255];
}

__global__ void fill_kernel() {
    int e = blockIdx.x * blockDim.x + threadIdx.x;
    if (e >= ETOT) return;
    int pos = atomicAdd(&g_cur[g_edst[e]], 1);
    g_srcs[pos] = g_esrc[e];
}

// ---------------- bf16-split warp MMA GEMM ----------------
// C[M x NC] = (Ahi+Alo)[M x K] @ ((Bhi+Blo)[NC x K])^T, 3 combos, fp32 accum.
// CTA tile 128 x BN, 8 warps (4 m x 2 n), warp tile 32 x BN/2, mma m16n8k16.
// AFP32: A arrives as fp32 and is split to bf16 hi/lo in-register (fused conv).
// Fused epilogue: atomicAdd partial alpha_src/alpha_dst dots per row.
#define KC    32
#define KPAD  40                          // 80B row stride, conflict-free fragments
#define ABYTES (128 * KPAD * 2)           // 10240

__device__ __forceinline__ void mma16816(float* c, const uint32_t* a, const uint32_t* b) {
    asm volatile(
        "mma.sync.aligned.m16n8k16.row.col.f32.bf16.bf16.f32 "
        "{%0,%1,%2,%3}, {%4,%5,%6,%7}, {%8,%9}, {%0,%1,%2,%3};"
        : "+f"(c[0]), "+f"(c[1]), "+f"(c[2]), "+f"(c[3])
        : "r"(a[0]), "r"(a[1]), "r"(a[2]), "r"(a[3]), "r"(b[0]), "r"(b[1]));
}

__device__ __forceinline__ uint32_t smem_u32(const void* p) {
    uint32_t a;
    asm("{ .reg .u64 t; cvta.to.shared.u64 t, %1; cvt.u32.u64 %0, t; }" : "=r"(a) : "l"(p));
    return a;
}
__device__ __forceinline__ void cp16(uint32_t dst, const void* src) {
    asm volatile("cp.async.cg.shared.global [%0], [%1], 16;" :: "r"(dst), "l"(src));
}

template <int NC, int BN, bool AFP32>
__global__ __launch_bounds__(256)
void gemm_mma_kernel(const void* __restrict__ Aarg, const __nv_bfloat16* __restrict__ Alo,
                     const __nv_bfloat16* __restrict__ Bhi, const __nv_bfloat16* __restrict__ Blo,
                     float* __restrict__ C,
                     const float* __restrict__ avs, const float* __restrict__ avd,
                     float* __restrict__ as_out, float* __restrict__ ad_out,
                     int M, int K) {
    constexpr int NT      = BN / 16;            // n-tiles per warp
    constexpr int BBYTES  = BN * KPAD * 2;
    constexpr int BUFB    = 2 * ABYTES + 2 * BBYTES;

    extern __shared__ char smem[];
    const uint32_t sb = smem_u32(smem);

    const int tid   = threadIdx.x;
    const int wid   = tid >> 5;
    const int lane  = tid & 31;
    const int wm    = wid & 3;
    const int wn    = wid >> 2;
    const int g     = lane >> 2;
    const int t     = lane & 3;
    const int m0    = blockIdx.y * 128;
    const int n0    = blockIdx.x * BN;

    const float* Af = (const float*)Aarg;
    const __nv_bfloat16* Ahi = (const __nv_bfloat16*)Aarg;

    pdl_trigger();          // let dependent kernel launch early
    pdl_wait();             // inputs may come from the immediately preceding kernel

    float acc[2][NT][4];
    #pragma unroll
    for (int i = 0; i < 2; i++)
        #pragma unroll
        for (int j = 0; j < NT; j++)
            #pragma unroll
            for (int q = 0; q < 4; q++) acc[i][j][q] = 0.0f;

    const int NCHUNK = K / KC;

    // fused-conversion A staging (AFP32): one thread = 16 contiguous fp32
    const int arowA = min(m0 + (tid >> 1), M - 1);
    const int halfA = tid & 1;
    float areg[AFP32 ? 16 : 1];

    auto ldgA = [&](int ch) {
        if constexpr (AFP32) {
            const float* p = Af + (size_t)arowA * K + ch * KC + halfA * 16;
            #pragma unroll
            for (int v = 0; v < 4; v++)
                *reinterpret_cast<float4*>(&areg[4 * v]) =
                    *reinterpret_cast<const float4*>(p + 4 * v);
        }
    };
    auto stsA = [&](int buf) {
        if constexpr (AFP32) {
            uint32_t hw[8], lw[8];
            #pragma unroll
            for (int i = 0; i < 8; i++)
                split_pair(areg[2 * i], areg[2 * i + 1], hw[i], lw[i]);
            char* base = smem + buf * BUFB + (tid >> 1) * (KPAD * 2) + halfA * 32;
            *reinterpret_cast<uint4*>(base)      = make_uint4(hw[0], hw[1], hw[2], hw[3]);
            *reinterpret_cast<uint4*>(base + 16) = make_uint4(hw[4], hw[5], hw[6], hw[7]);
            char* lbase = base + ABYTES;
            *reinterpret_cast<uint4*>(lbase)      = make_uint4(lw[0], lw[1], lw[2], lw[3]);
            *reinterpret_cast<uint4*>(lbase + 16) = make_uint4(lw[4], lw[5], lw[6], lw[7]);
        }
    };

    auto issue_chunk = [&](int ch, int buf) {
        const int kc0 = ch * KC;
        const uint32_t bbase = sb + buf * BUFB;
        if constexpr (!AFP32) {
            #pragma unroll
            for (int it = 0; it < 2; it++) {                // A: 128 rows x 4 slots
                const int idx = tid + it * 256;
                const int row = idx >> 2;
                const int c4  = idx & 3;
                const int arow = min(m0 + row, M - 1);      // clamp; garbage rows unsaved
                const size_t ao = (size_t)arow * K + kc0 + c4 * 8;
                const uint32_t so = (uint32_t)(row * (KPAD * 2) + c4 * 16);
                cp16(bbase + so, Ahi + ao);
                cp16(bbase + ABYTES + so, Alo + ao);
            }
        }
        #pragma unroll
        for (int it = 0; it < BN * 4 / 256; it++) {         // B: BN rows x 4 slots
            const int idx = tid + it * 256;
            const int row = idx >> 2;
            const int c4  = idx & 3;
            const size_t bo = (size_t)(n0 + row) * K + kc0 + c4 * 8;  // NC mult of BN
            const uint32_t so = (uint32_t)(row * (KPAD * 2) + c4 * 16);
            cp16(bbase + 2 * ABYTES + so, Bhi + bo);
            cp16(bbase + 2 * ABYTES + BBYTES + so, Blo + bo);
        }
        asm volatile("cp.async.commit_group;" ::: "memory");
    };

    // prologue
    ldgA(0);
    issue_chunk(0, 0);
    stsA(0);

    for (int ch = 0; ch < NCHUNK; ch++) {
        const int buf = ch & 1;
        const bool more = (ch + 1 < NCHUNK);
        if (more) {
            ldgA(ch + 1);
            issue_chunk(ch + 1, buf ^ 1);
        }
        if (more) asm volatile("cp.async.wait_group 1;" ::: "memory");
        else      asm volatile("cp.async.wait_group 0;" ::: "memory");
        __syncthreads();

        const char* pbuf = smem + buf * BUFB;
        #pragma unroll
        for (int ks = 0; ks < KC / 16; ks++) {
            const int kb = ks * 16;
            #pragma unroll
            for (int combo = 0; combo < 3; combo++) {
                const char* pA = pbuf + ((combo == 2) ? ABYTES : 0);
                const char* pB = pbuf + 2 * ABYTES + ((combo == 1) ? BBYTES : 0);

                uint32_t afrag[2][4];
                #pragma unroll
                for (int mt = 0; mt < 2; mt++) {
                    const int r0 = wm * 32 + mt * 16 + g;
                    const char* q0 = pA + r0 * (KPAD * 2) + (kb + 2 * t) * 2;
                    const char* q1 = pA + (r0 + 8) * (KPAD * 2) + (kb + 2 * t) * 2;
                    afrag[mt][0] = *reinterpret_cast<const uint32_t*>(q0);
                    afrag[mt][1] = *reinterpret_cast<const uint32_t*>(q1);
                    afrag[mt][2] = *reinterpret_cast<const uint32_t*>(q0 + 16);
                    afrag[mt][3] = *reinterpret_cast<const uint32_t*>(q1 + 16);
                }
                uint32_t bfrag[NT][2];
                #pragma unroll
                for (int nt = 0; nt < NT; nt++) {
                    const int n = wn * (BN / 2) + nt * 8 + g;
                    const char* q = pB + n * (KPAD * 2) + (kb + 2 * t) * 2;
                    bfrag[nt][0] = *reinterpret_cast<const uint32_t*>(q);
                    bfrag[nt][1] = *reinterpret_cast<const uint32_t*>(q + 16);
                }
                #pragma unroll
                for (int mt = 0; mt < 2; mt++)
                    #pragma unroll
                    for (int nt = 0; nt < NT; nt++)
                        mma16816(acc[mt][nt], afrag[mt], bfrag[nt]);
            }
        }
        if (more) stsA(buf ^ 1);   // visible after next iteration's __syncthreads
        __syncthreads();           // buf free for reuse
    }

    // ---- epilogue: store C + fused partial alpha dots ----
    float sa[4] = {0.f, 0.f, 0.f, 0.f};   // rows: wm*32 + {0,8,16,24} + g
    float da[4] = {0.f, 0.f, 0.f, 0.f};
    #pragma unroll
    for (int mt = 0; mt < 2; mt++) {
        const int r0 = m0 + wm * 32 + mt * 16 + g;
        #pragma unroll
        for (int nt = 0; nt < NT; nt++) {
            const int col = n0 + wn * (BN / 2) + nt * 8 + 2 * t;
            const float v0 = avs[col], v1 = avs[col + 1];
            const float u0 = avd[col], u1 = avd[col + 1];
            sa[2 * mt]     += acc[mt][nt][0] * v0 + acc[mt][nt][1] * v1;
            da[2 * mt]     += acc[mt][nt][0] * u0 + acc[mt][nt][1] * u1;
            sa[2 * mt + 1] += acc[mt][nt][2] * v0 + acc[mt][nt][3] * v1;
            da[2 * mt + 1] += acc[mt][nt][2] * u0 + acc[mt][nt][3] * u1;
            if (r0 < M)
                *reinterpret_cast<float2*>(&C[(size_t)r0 * NC + col]) =
                    make_float2(acc[mt][nt][0], acc[mt][nt][1]);
            if (r0 + 8 < M)
                *reinterpret_cast<float2*>(&C[(size_t)(r0 + 8) * NC + col]) =
                    make_float2(acc[mt][nt][2], acc[mt][nt][3]);
        }
    }
    #pragma unroll
    for (int q = 0; q < 4; q++) {
        sa[q] += __shfl_xor_sync(0xffffffffu, sa[q], 1);
        sa[q] += __shfl_xor_sync(0xffffffffu, sa[q], 2);
        da[q] += __shfl_xor_sync(0xffffffffu, da[q], 1);
        da[q] += __shfl_xor_sync(0xffffffffu, da[q], 2);
    }
    if (t == 0) {
        #pragma unroll
        for (int q = 0; q < 4; q++) {
            const int r = m0 + wm * 32 + q * 8 + g;
            if (r < M) {
                atomicAdd(&as_out[r], sa[q]);
                atomicAdd(&ad_out[r], da[q]);
            }
        }
    }
}

// ---------------- fused softmax + aggregation: one block per dst, float4 ----------------
// blockDim = C/4; each thread owns 4 channels, gathers with one float4 per edge
// (4x fewer warp-LDGs than scalar). No max-subtraction: logits ~ N(0, sqrt(2));
// exp is overflow-safe and the softmax ratio is mathematically identical.
template <int C, bool BF16OUT>
__global__ void aggregate_kernel(const float* __restrict__ h,
                                 const float* __restrict__ bias,
                                 const float* __restrict__ as_in,
                                 const float* __restrict__ ad_in,
                                 float* __restrict__ out) {
    constexpr int TH = C / 4;
    __shared__ float ws[TH];
    __shared__ int   ss[TH];
    const int d   = blockIdx.x;
    const int tid = threadIdx.x;

    pdl_trigger();
    // PDL prologue: CSR data (g_off/g_srcs) is guaranteed by the event edge,
    // not by the immediately preceding kernel, so stage it before pdl_wait.
    const int beg = g_off[d];
    const int end = g_off[d + 1];
    float ad = 0.0f;
    bool waited = false;

    float4 acc = make_float4(0.f, 0.f, 0.f, 0.f);
    float den = 0.0f;
    for (int cbeg = beg; cbeg < end; cbeg += TH) {
        const int nchunk = min(TH, end - cbeg);
        __syncthreads();
        int s = -1;
        if (tid < nchunk) {
            s = g_srcs[cbeg + tid];
            ss[tid] = s;
        }
        if (!waited) {           // first iteration: wait for h / as / ad producers
            pdl_wait();
            ad = ad_in[d];
            waited = true;
        }
        if (tid < nchunk) {
            float tt = as_in[s] + ad;
            float l = tt > 0.0f ? tt : NEG_SLOPE * tt;
            ws[tid] = __expf(l);
        }
        __syncthreads();
        for (int jj = 0; jj < nchunk; jj++) {
            const float w = ws[jj];
            den += w;
            const float4 hv = *reinterpret_cast<const float4*>(
                &h[(size_t)ss[jj] * C + 4 * tid]);
            acc.x += w * hv.x;
            acc.y += w * hv.y;
            acc.z += w * hv.z;
            acc.w += w * hv.w;
        }
    }

    const float inv = 1.0f / den;
    const float4 bv = *reinterpret_cast<const float4*>(&bias[4 * tid]);
    float4 r;
    r.x = acc.x * inv + bv.x;
    r.y = acc.y * inv + bv.y;
    r.z = acc.z * inv + bv.z;
    r.w = acc.w * inv + bv.w;
    if (BF16OUT) {
        r.x = fmaxf(r.x, 0.f); r.y = fmaxf(r.y, 0.f);
        r.z = fmaxf(r.z, 0.f); r.w = fmaxf(r.w, 0.f);
        uint32_t h01, l01, h23, l23;
        split_pair(r.x, r.y, h01, l01);
        split_pair(r.z, r.w, h23, l23);
        *reinterpret_cast<uint2*>(&g_thi[(size_t)d * C + 4 * tid]) = make_uint2(h01, h23);
        *reinterpret_cast<uint2*>(&g_tlo[(size_t)d * C + 4 * tid]) = make_uint2(l01, l23);
    } else {
        *reinterpret_cast<float4*>(&out[(size_t)d * C + 4 * tid]) = r;
    }
}

// ---------------- launch ----------------
extern "C" void kernel_launch(void* const* d_in, const int* in_sizes, int n_in,
                              void* d_out, int out_size) {
    const float* x   = (const float*)d_in[0];
    const void*  ei  = (const void*)d_in[1];
    const float* W1  = (const float*)d_in[2];
    const float* as1 = (const float*)d_in[3];
    const float* ad1 = (const float*)d_in[4];
    const float* b1  = (const float*)d_in[5];
    const float* W2  = (const float*)d_in[6];
    const float* as2 = (const float*)d_in[7];
    const float* ad2 = (const float*)d_in[8];
    const float* b2  = (const float*)d_in[9];
    float* out = (float*)d_out;

    float *g_h_p, *pas1, *pad1, *pas2, *pad2;
    cudaGetSymbolAddress((void**)&g_h_p, g_h);
    cudaGetSymbolAddress((void**)&pas1, g_as1);
    cudaGetSymbolAddress((void**)&pad1, g_ad1);
    cudaGetSymbolAddress((void**)&pas2, g_as2);
    cudaGetSymbolAddress((void**)&pad2, g_ad2);
    __nv_bfloat16 *thi, *tlo, *w1hi, *w1lo, *w2hi, *w2lo;
    cudaGetSymbolAddress((void**)&thi, g_thi);   cudaGetSymbolAddress((void**)&tlo, g_tlo);
    cudaGetSymbolAddress((void**)&w1hi, g_w1hi); cudaGetSymbolAddress((void**)&w1lo, g_w1lo);
    cudaGetSymbolAddress((void**)&w2hi, g_w2hi); cudaGetSymbolAddress((void**)&w2lo, g_w2lo);

    constexpr int SMEM64 = 2 * (2 * ABYTES + 2 * (64 * KPAD * 2));   // 61440

    // one-time host objects (no device memory involved)
    static cudaStream_t sCSR = nullptr;
    static cudaEvent_t evFork = nullptr, evCSR = nullptr;
    if (sCSR == nullptr) {
        cudaFuncSetAttribute(gemm_mma_kernel<CHID, 64, true>,
                             cudaFuncAttributeMaxDynamicSharedMemorySize, SMEM64);
        cudaFuncSetAttribute(gemm_mma_kernel<COUT, 64, false>,
                             cudaFuncAttributeMaxDynamicSharedMemorySize, SMEM64);
        cudaStreamCreateWithFlags(&sCSR, cudaStreamNonBlocking);
        cudaEventCreateWithFlags(&evFork, cudaEventDisableTiming);
        cudaEventCreateWithFlags(&evCSR, cudaEventDisableTiming);
    }

    const int TPB = 256;
    const int nblk_edges = (ETOT + TPB - 1) / TPB;
    const int MTILES = (NNODES + 127) / 128;   // 157

    // PDL launch config (used on agg1->gemm2 and gemm2->agg2 adjacencies)
    cudaLaunchAttribute pdlAttr[1];
    pdlAttr[0].id = cudaLaunchAttributeProgrammaticStreamSerialization;
    pdlAttr[0].val.programmaticStreamSerializationAllowed = 1;

    // ---- stream 0: setup (init + detect + weight conversion) ----
    setup_kernel<<<NBLK_N + NBLK_W, TPB>>>(ei, W1, W2);
    cudaEventRecord(evFork, 0);

    // ---- CSR branch (sCSR) ----
    cudaStreamWaitEvent(sCSR, evFork, 0);
    convert_count_kernel<<<nblk_edges, TPB, 0, sCSR>>>(ei);
    scan_part_kernel<<<NBLK_N, 256, 0, sCSR>>>();
    scan_write_kernel<<<NBLK_N, 256, 0, sCSR>>>();
    fill_kernel<<<nblk_edges, TPB, 0, sCSR>>>();
    cudaEventRecord(evCSR, sCSR);

    // ---- main: GEMM1 (fp32 x, fused bf16 split; weights ready in-stream) ----
    {
        dim3 grid(CHID / 64, MTILES);
        gemm_mma_kernel<CHID, 64, true><<<grid, 256, SMEM64>>>(
            (const void*)x, nullptr, w1hi, w1lo, g_h_p, as1, ad1, pas1, pad1,
            NNODES, CIN);
    }

    // ---- join CSR, aggregate1 ----
    cudaStreamWaitEvent(0, evCSR, 0);
    aggregate_kernel<CHID, true><<<NNODES, CHID / 4>>>(g_h_p, b1, pas1, pad1, nullptr);

    // ---- layer 2 (PDL chained: agg1 -> gemm2 -> agg2) ----
    {
        cudaLaunchConfig_t cfg = {};
        cfg.gridDim = dim3(COUT / 64, MTILES);
        cfg.blockDim = dim3(256, 1, 1);
        cfg.dynamicSmemBytes = SMEM64;
        cfg.stream = 0;
        cfg.attrs = pdlAttr;
        cfg.numAttrs = 1;
        int M = NNODES, K = CHID;
        cudaLaunchKernelEx(&cfg, gemm_mma_kernel<COUT, 64, false>,
                           (const void*)thi, (const __nv_bfloat16*)tlo,
                           (const __nv_bfloat16*)w2hi, (const __nv_bfloat16*)w2lo,
                           (float*)g_h_p, (const float*)as2, (const float*)ad2,
                           (float*)pas2, (float*)pad2, M, K);
    }
    {
        cudaLaunchConfig_t cfg = {};
        cfg.gridDim = dim3(NNODES, 1, 1);
        cfg.blockDim = dim3(COUT / 4, 1, 1);
        cfg.dynamicSmemBytes = 0;
        cfg.stream = 0;
        cfg.attrs = pdlAttr;
        cfg.numAttrs = 1;
        cudaLaunchKernelEx(&cfg, aggregate_kernel<COUT, false>,
                           (const float*)g_h_p, (const float*)b2,
                           (const float*)pas2, (const float*)pad2, (float*)out);
    }
}

// round 14
// speedup vs baseline: 1.4019x; 1.0325x over previous
#include <cuda_runtime.h>
#include <cuda_bf16.h>
#include <math_constants.h>
#include <cstdint>

// ---------------- problem constants ----------------
#define NNODES 20000
#define NEDGES 320000
#define ETOT   (NEDGES + NNODES)   // + self loops
#define CIN    256
#define CHID   256
#define COUT   128
#define NEG_SLOPE 0.2f
#define NBLK_N ((NNODES + 255) / 256)   // 79
#define CONVW_ELEMS (CIN * CHID + CHID * COUT)          // 98304
#define NBLK_W ((CONVW_ELEMS + 255) / 256)              // 384

// ---------------- device scratch (no allocations allowed) ----------------
__device__ float g_h[NNODES * CHID];     // GEMM output of current layer
__device__ float g_as1[NNODES];
__device__ float g_ad1[NNODES];
__device__ float g_as2[NNODES];
__device__ float g_ad2[NNODES];
__device__ int   g_deg[NNODES];
__device__ int   g_bsum[NBLK_N];
__device__ int   g_off[NNODES + 1];
__device__ int   g_cur[NNODES];
__device__ int   g_srcs[ETOT];
__device__ int   g_esrc[ETOT];
__device__ int   g_edst[ETOT];
__device__ int   g_is64;

// bf16 split operands (weights + layer-2 activations; x converts inside GEMM1)
__device__ __nv_bfloat16 g_thi[NNODES * CHID];   // layer-2 input (written by aggregate1)
__device__ __nv_bfloat16 g_tlo[NNODES * CHID];
__device__ __nv_bfloat16 g_w1hi[CHID * CIN];     // W1^T : [N=CHID][K=CIN]
__device__ __nv_bfloat16 g_w1lo[CHID * CIN];
__device__ __nv_bfloat16 g_w2hi[COUT * CHID];    // W2^T : [N=COUT][K=CHID]
__device__ __nv_bfloat16 g_w2lo[COUT * CHID];

// ---------------- PDL helpers (no-ops when not PDL-launched) ----------------
__device__ __forceinline__ void pdl_trigger() {
    asm volatile("griddepcontrol.launch_dependents;" ::: "memory");
}
__device__ __forceinline__ void pdl_wait() {
    asm volatile("griddepcontrol.wait;" ::: "memory");
}

// ---------------- split helpers ----------------
__device__ __forceinline__ void bf16_split(float v, __nv_bfloat16& hi, __nv_bfloat16& lo) {
    hi = __float2bfloat16(v);
    lo = __float2bfloat16(v - __bfloat162float(hi));
}
__device__ __forceinline__ void split_pair(float v0, float v1,
                                           uint32_t& hw, uint32_t& lw) {
    __nv_bfloat16 h0, l0, h1, l1;
    bf16_split(v0, h0, l0);
    bf16_split(v1, h1, l1);
    hw = ((uint32_t)__bfloat16_as_ushort(h1) << 16) | __bfloat16_as_ushort(h0);
    lw = ((uint32_t)__bfloat16_as_ushort(l1) << 16) | __bfloat16_as_ushort(l0);
}

// ---------------- setup: detect dtype + zero init + weight conversion ----------------
__global__ void setup_kernel(const void* __restrict__ ei,
                             const float* __restrict__ W1,
                             const float* __restrict__ W2) {
    const int b = blockIdx.x;
    if (b < NBLK_N) {
        int i = b * blockDim.x + threadIdx.x;
        if (i < NNODES) {
            g_deg[i] = 0;
            g_as1[i] = 0.f; g_ad1[i] = 0.f;
            g_as2[i] = 0.f; g_ad2[i] = 0.f;
        }
        if (b == 0) {
            const long long* p = (const long long*)ei;
            int bad = 0;
            #pragma unroll
            for (int k = threadIdx.x; k < 2048; k += 256) {
                long long v = p[k];
                if (v < 0 || v >= NNODES) bad = 1;
            }
            int anybad = __syncthreads_or(bad);
            if (threadIdx.x == 0) g_is64 = !anybad;
        }
    } else {
        int i = (b - NBLK_N) * blockDim.x + threadIdx.x;
        if (i < CIN * CHID) {
            int k = i / CHID, n = i % CHID;           // W1[k][n] -> w1t[n][k]
            bf16_split(W1[i], g_w1hi[n * CIN + k], g_w1lo[n * CIN + k]);
        } else if (i < CONVW_ELEMS) {
            int j = i - CIN * CHID;
            int k = j / COUT, n = j % COUT;           // W2[k][n] -> w2t[n][k]
            bf16_split(W2[j], g_w2hi[n * CHID + k], g_w2lo[n * CHID + k]);
        }
    }
    pdl_trigger();   // dependent (GEMM1) may begin launching; it pdl_waits before reads
}

// ---------------- convert + degree count ----------------
__global__ void convert_count_kernel(const void* __restrict__ ei) {
    int e = blockIdx.x * blockDim.x + threadIdx.x;
    if (e >= ETOT) return;
    int s, d;
    if (e < NEDGES) {
        if (g_is64) {
            const long long* p = (const long long*)ei;
            s = (int)p[e]; d = (int)p[NEDGES + e];
        } else {
            const int* p = (const int*)ei;
            s = p[e]; d = p[NEDGES + e];
        }
    } else {
        s = e - NEDGES; d = s;
    }
    g_esrc[e] = s;
    g_edst[e] = d;
    atomicAdd(&g_deg[d], 1);
}

// ---------------- multi-block scan ----------------
__global__ void scan_part_kernel() {
    __shared__ int sh[256];
    int i = blockIdx.x * 256 + threadIdx.x;
    sh[threadIdx.x] = (i < NNODES) ? g_deg[i] : 0;
    __syncthreads();
    #pragma unroll
    for (int st = 128; st > 0; st >>= 1) {
        if (threadIdx.x < st) sh[threadIdx.x] += sh[threadIdx.x + st];
        __syncthreads();
    }
    if (threadIdx.x == 0) g_bsum[blockIdx.x] = sh[0];
}

__global__ void scan_write_kernel() {
    __shared__ int sh[256];
    __shared__ int base_sh;
    const int t = threadIdx.x;
    const int b = blockIdx.x;
    int pv = (t < b && t < NBLK_N) ? g_bsum[t] : 0;
    sh[t] = pv;
    __syncthreads();
    #pragma unroll
    for (int st = 128; st > 0; st >>= 1) {
        if (t < st) sh[t] += sh[t + st];
        __syncthreads();
    }
    if (t == 0) base_sh = sh[0];
    __syncthreads();
    const int base = base_sh;
    __syncthreads();
    int i = b * 256 + t;
    int d = (i < NNODES) ? g_deg[i] : 0;
    sh[t] = d;
    __syncthreads();
    #pragma unroll
    for (int st = 1; st < 256; st <<= 1) {
        int v = (t >= st) ? sh[t - st] : 0;
        __syncthreads();
        sh[t] += v;
        __syncthreads();
    }
    if (i < NNODES) {
        int off = base + sh[t] - d;
        g_off[i] = off;
        g_cur[i] = off;
    }
    if (b == NBLK_N - 1 && t == 255) g_off[NNODES] = base + sh[255];
}

__global__ void fill_kernel() {
    int e = blockIdx.x * blockDim.x + threadIdx.x;
    if (e >= ETOT) return;
    int pos = atomicAdd(&g_cur[g_edst[e]], 1);
    g_srcs[pos] = g_esrc[e];
}

// ---------------- bf16-split warp MMA GEMM ----------------
// C[M x NC] = (Ahi+Alo)[M x K] @ ((Bhi+Blo)[NC x K])^T, 3 combos, fp32 accum.
// CTA tile 128 x BN, 8 warps (4 m x 2 n), warp tile 32 x BN/2, mma m16n8k16.
// AFP32: A arrives as fp32 and is split to bf16 hi/lo in-register (fused conv).
// Fused epilogue: atomicAdd partial alpha_src/alpha_dst dots per row.
#define KC    32
#define KPAD  40                          // 80B row stride, conflict-free fragments
#define ABYTES (128 * KPAD * 2)           // 10240

__device__ __forceinline__ void mma16816(float* c, const uint32_t* a, const uint32_t* b) {
    asm volatile(
        "mma.sync.aligned.m16n8k16.row.col.f32.bf16.bf16.f32 "
        "{%0,%1,%2,%3}, {%4,%5,%6,%7}, {%8,%9}, {%0,%1,%2,%3};"
        : "+f"(c[0]), "+f"(c[1]), "+f"(c[2]), "+f"(c[3])
        : "r"(a[0]), "r"(a[1]), "r"(a[2]), "r"(a[3]), "r"(b[0]), "r"(b[1]));
}

__device__ __forceinline__ uint32_t smem_u32(const void* p) {
    uint32_t a;
    asm("{ .reg .u64 t; cvta.to.shared.u64 t, %1; cvt.u32.u64 %0, t; }" : "=r"(a) : "l"(p));
    return a;
}
__device__ __forceinline__ void cp16(uint32_t dst, const void* src) {
    asm volatile("cp.async.cg.shared.global [%0], [%1], 16;" :: "r"(dst), "l"(src));
}

template <int NC, int BN, bool AFP32>
__global__ __launch_bounds__(256)
void gemm_mma_kernel(const void* __restrict__ Aarg, const __nv_bfloat16* __restrict__ Alo,
                     const __nv_bfloat16* __restrict__ Bhi, const __nv_bfloat16* __restrict__ Blo,
                     float* __restrict__ C,
                     const float* __restrict__ avs, const float* __restrict__ avd,
                     float* __restrict__ as_out, float* __restrict__ ad_out,
                     int M, int K) {
    constexpr int NT      = BN / 16;            // n-tiles per warp
    constexpr int BBYTES  = BN * KPAD * 2;
    constexpr int BUFB    = 2 * ABYTES + 2 * BBYTES;

    extern __shared__ char smem[];
    const uint32_t sb = smem_u32(smem);

    const int tid   = threadIdx.x;
    const int wid   = tid >> 5;
    const int lane  = tid & 31;
    const int wm    = wid & 3;
    const int wn    = wid >> 2;
    const int g     = lane >> 2;
    const int t     = lane & 3;
    const int m0    = blockIdx.y * 128;
    const int n0    = blockIdx.x * BN;

    const float* Af = (const float*)Aarg;
    const __nv_bfloat16* Ahi = (const __nv_bfloat16*)Aarg;

    pdl_trigger();          // let dependent kernel launch early
    pdl_wait();             // inputs may come from the immediately preceding kernel

    float acc[2][NT][4];
    #pragma unroll
    for (int i = 0; i < 2; i++)
        #pragma unroll
        for (int j = 0; j < NT; j++)
            #pragma unroll
            for (int q = 0; q < 4; q++) acc[i][j][q] = 0.0f;

    const int NCHUNK = K / KC;

    // fused-conversion A staging (AFP32): one thread = 16 contiguous fp32
    const int arowA = min(m0 + (tid >> 1), M - 1);
    const int halfA = tid & 1;
    float areg[AFP32 ? 16 : 1];

    auto ldgA = [&](int ch) {
        if constexpr (AFP32) {
            const float* p = Af + (size_t)arowA * K + ch * KC + halfA * 16;
            #pragma unroll
            for (int v = 0; v < 4; v++)
                *reinterpret_cast<float4*>(&areg[4 * v]) =
                    *reinterpret_cast<const float4*>(p + 4 * v);
        }
    };
    auto stsA = [&](int buf) {
        if constexpr (AFP32) {
            uint32_t hw[8], lw[8];
            #pragma unroll
            for (int i = 0; i < 8; i++)
                split_pair(areg[2 * i], areg[2 * i + 1], hw[i], lw[i]);
            char* base = smem + buf * BUFB + (tid >> 1) * (KPAD * 2) + halfA * 32;
            *reinterpret_cast<uint4*>(base)      = make_uint4(hw[0], hw[1], hw[2], hw[3]);
            *reinterpret_cast<uint4*>(base + 16) = make_uint4(hw[4], hw[5], hw[6], hw[7]);
            char* lbase = base + ABYTES;
            *reinterpret_cast<uint4*>(lbase)      = make_uint4(lw[0], lw[1], lw[2], lw[3]);
            *reinterpret_cast<uint4*>(lbase + 16) = make_uint4(lw[4], lw[5], lw[6], lw[7]);
        }
    };

    auto issue_chunk = [&](int ch, int buf) {
        const int kc0 = ch * KC;
        const uint32_t bbase = sb + buf * BUFB;
        if constexpr (!AFP32) {
            #pragma unroll
            for (int it = 0; it < 2; it++) {                // A: 128 rows x 4 slots
                const int idx = tid + it * 256;
                const int row = idx >> 2;
                const int c4  = idx & 3;
                const int arow = min(m0 + row, M - 1);      // clamp; garbage rows unsaved
                const size_t ao = (size_t)arow * K + kc0 + c4 * 8;
                const uint32_t so = (uint32_t)(row * (KPAD * 2) + c4 * 16);
                cp16(bbase + so, Ahi + ao);
                cp16(bbase + ABYTES + so, Alo + ao);
            }
        }
        #pragma unroll
        for (int it = 0; it < BN * 4 / 256; it++) {         // B: BN rows x 4 slots
            const int idx = tid + it * 256;
            const int row = idx >> 2;
            const int c4  = idx & 3;
            const size_t bo = (size_t)(n0 + row) * K + kc0 + c4 * 8;  // NC mult of BN
            const uint32_t so = (uint32_t)(row * (KPAD * 2) + c4 * 16);
            cp16(bbase + 2 * ABYTES + so, Bhi + bo);
            cp16(bbase + 2 * ABYTES + BBYTES + so, Blo + bo);
        }
        asm volatile("cp.async.commit_group;" ::: "memory");
    };

    // prologue
    ldgA(0);
    issue_chunk(0, 0);
    stsA(0);

    for (int ch = 0; ch < NCHUNK; ch++) {
        const int buf = ch & 1;
        const bool more = (ch + 1 < NCHUNK);
        if (more) {
            ldgA(ch + 1);
            issue_chunk(ch + 1, buf ^ 1);
        }
        if (more) asm volatile("cp.async.wait_group 1;" ::: "memory");
        else      asm volatile("cp.async.wait_group 0;" ::: "memory");
        __syncthreads();

        const char* pbuf = smem + buf * BUFB;
        #pragma unroll
        for (int ks = 0; ks < KC / 16; ks++) {
            const int kb = ks * 16;
            #pragma unroll
            for (int combo = 0; combo < 3; combo++) {
                const char* pA = pbuf + ((combo == 2) ? ABYTES : 0);
                const char* pB = pbuf + 2 * ABYTES + ((combo == 1) ? BBYTES : 0);

                uint32_t afrag[2][4];
                #pragma unroll
                for (int mt = 0; mt < 2; mt++) {
                    const int r0 = wm * 32 + mt * 16 + g;
                    const char* q0 = pA + r0 * (KPAD * 2) + (kb + 2 * t) * 2;
                    const char* q1 = pA + (r0 + 8) * (KPAD * 2) + (kb + 2 * t) * 2;
                    afrag[mt][0] = *reinterpret_cast<const uint32_t*>(q0);
                    afrag[mt][1] = *reinterpret_cast<const uint32_t*>(q1);
                    afrag[mt][2] = *reinterpret_cast<const uint32_t*>(q0 + 16);
                    afrag[mt][3] = *reinterpret_cast<const uint32_t*>(q1 + 16);
                }
                uint32_t bfrag[NT][2];
                #pragma unroll
                for (int nt = 0; nt < NT; nt++) {
                    const int n = wn * (BN / 2) + nt * 8 + g;
                    const char* q = pB + n * (KPAD * 2) + (kb + 2 * t) * 2;
                    bfrag[nt][0] = *reinterpret_cast<const uint32_t*>(q);
                    bfrag[nt][1] = *reinterpret_cast<const uint32_t*>(q + 16);
                }
                #pragma unroll
                for (int mt = 0; mt < 2; mt++)
                    #pragma unroll
                    for (int nt = 0; nt < NT; nt++)
                        mma16816(acc[mt][nt], afrag[mt], bfrag[nt]);
            }
        }
        if (more) stsA(buf ^ 1);   // visible after next iteration's __syncthreads
        __syncthreads();           // buf free for reuse
    }

    // ---- epilogue: store C + fused partial alpha dots ----
    float sa[4] = {0.f, 0.f, 0.f, 0.f};   // rows: wm*32 + {0,8,16,24} + g
    float da[4] = {0.f, 0.f, 0.f, 0.f};
    #pragma unroll
    for (int mt = 0; mt < 2; mt++) {
        const int r0 = m0 + wm * 32 + mt * 16 + g;
        #pragma unroll
        for (int nt = 0; nt < NT; nt++) {
            const int col = n0 + wn * (BN / 2) + nt * 8 + 2 * t;
            const float v0 = avs[col], v1 = avs[col + 1];
            const float u0 = avd[col], u1 = avd[col + 1];
            sa[2 * mt]     += acc[mt][nt][0] * v0 + acc[mt][nt][1] * v1;
            da[2 * mt]     += acc[mt][nt][0] * u0 + acc[mt][nt][1] * u1;
            sa[2 * mt + 1] += acc[mt][nt][2] * v0 + acc[mt][nt][3] * v1;
            da[2 * mt + 1] += acc[mt][nt][2] * u0 + acc[mt][nt][3] * u1;
            if (r0 < M)
                *reinterpret_cast<float2*>(&C[(size_t)r0 * NC + col]) =
                    make_float2(acc[mt][nt][0], acc[mt][nt][1]);
            if (r0 + 8 < M)
                *reinterpret_cast<float2*>(&C[(size_t)(r0 + 8) * NC + col]) =
                    make_float2(acc[mt][nt][2], acc[mt][nt][3]);
        }
    }
    #pragma unroll
    for (int q = 0; q < 4; q++) {
        sa[q] += __shfl_xor_sync(0xffffffffu, sa[q], 1);
        sa[q] += __shfl_xor_sync(0xffffffffu, sa[q], 2);
        da[q] += __shfl_xor_sync(0xffffffffu, da[q], 1);
        da[q] += __shfl_xor_sync(0xffffffffu, da[q], 2);
    }
    if (t == 0) {
        #pragma unroll
        for (int q = 0; q < 4; q++) {
            const int r = m0 + wm * 32 + q * 8 + g;
            if (r < M) {
                atomicAdd(&as_out[r], sa[q]);
                atomicAdd(&ad_out[r], da[q]);
            }
        }
    }
}

// ---------------- fused softmax + aggregation: one block per dst, float4 ----------------
// blockDim = C/4; each thread owns 4 channels, gathers with one float4 per edge.
// 2-way unrolled inner loop with independent accumulators (hide FMA+L2 latency).
// No max-subtraction: logits ~ N(0, sqrt(2)); exp is overflow-safe and the
// softmax ratio is mathematically identical.
template <int C, bool BF16OUT>
__global__ void aggregate_kernel(const float* __restrict__ h,
                                 const float* __restrict__ bias,
                                 const float* __restrict__ as_in,
                                 const float* __restrict__ ad_in,
                                 float* __restrict__ out) {
    constexpr int TH = C / 4;
    __shared__ float ws[TH];
    __shared__ int   ss[TH];
    const int d   = blockIdx.x;
    const int tid = threadIdx.x;

    pdl_trigger();
    // PDL prologue: CSR data (g_off/g_srcs) is guaranteed by the event edge,
    // not by the immediately preceding kernel, so stage it before pdl_wait.
    const int beg = g_off[d];
    const int end = g_off[d + 1];
    float ad = 0.0f;
    bool waited = false;

    float4 acc0 = make_float4(0.f, 0.f, 0.f, 0.f);
    float4 acc1 = make_float4(0.f, 0.f, 0.f, 0.f);
    float den0 = 0.0f, den1 = 0.0f;
    for (int cbeg = beg; cbeg < end; cbeg += TH) {
        const int nchunk = min(TH, end - cbeg);
        __syncthreads();
        int s = -1;
        if (tid < nchunk) {
            s = g_srcs[cbeg + tid];
            ss[tid] = s;
        }
        if (!waited) {           // first iteration: wait for h / as / ad producers
            pdl_wait();
            ad = ad_in[d];
            waited = true;
        }
        if (tid < nchunk) {
            float tt = as_in[s] + ad;
            float l = tt > 0.0f ? tt : NEG_SLOPE * tt;
            ws[tid] = __expf(l);
        }
        __syncthreads();
        int jj = 0;
        for (; jj + 2 <= nchunk; jj += 2) {
            const float w0 = ws[jj];
            const float w1 = ws[jj + 1];
            const float4 hv0 = *reinterpret_cast<const float4*>(
                &h[(size_t)ss[jj] * C + 4 * tid]);
            const float4 hv1 = *reinterpret_cast<const float4*>(
                &h[(size_t)ss[jj + 1] * C + 4 * tid]);
            den0 += w0; den1 += w1;
            acc0.x += w0 * hv0.x;  acc1.x += w1 * hv1.x;
            acc0.y += w0 * hv0.y;  acc1.y += w1 * hv1.y;
            acc0.z += w0 * hv0.z;  acc1.z += w1 * hv1.z;
            acc0.w += w0 * hv0.w;  acc1.w += w1 * hv1.w;
        }
        if (jj < nchunk) {
            const float w = ws[jj];
            const float4 hv = *reinterpret_cast<const float4*>(
                &h[(size_t)ss[jj] * C + 4 * tid]);
            den0 += w;
            acc0.x += w * hv.x; acc0.y += w * hv.y;
            acc0.z += w * hv.z; acc0.w += w * hv.w;
        }
    }

    const float inv = 1.0f / (den0 + den1);
    const float4 bv = *reinterpret_cast<const float4*>(&bias[4 * tid]);
    float4 r;
    r.x = (acc0.x + acc1.x) * inv + bv.x;
    r.y = (acc0.y + acc1.y) * inv + bv.y;
    r.z = (acc0.z + acc1.z) * inv + bv.z;
    r.w = (acc0.w + acc1.w) * inv + bv.w;
    if (BF16OUT) {
        r.x = fmaxf(r.x, 0.f); r.y = fmaxf(r.y, 0.f);
        r.z = fmaxf(r.z, 0.f); r.w = fmaxf(r.w, 0.f);
        uint32_t h01, l01, h23, l23;
        split_pair(r.x, r.y, h01, l01);
        split_pair(r.z, r.w, h23, l23);
        *reinterpret_cast<uint2*>(&g_thi[(size_t)d * C + 4 * tid]) = make_uint2(h01, h23);
        *reinterpret_cast<uint2*>(&g_tlo[(size_t)d * C + 4 * tid]) = make_uint2(l01, l23);
    } else {
        *reinterpret_cast<float4*>(&out[(size_t)d * C + 4 * tid]) = r;
    }
}

// ---------------- launch ----------------
extern "C" void kernel_launch(void* const* d_in, const int* in_sizes, int n_in,
                              void* d_out, int out_size) {
    const float* x   = (const float*)d_in[0];
    const void*  ei  = (const void*)d_in[1];
    const float* W1  = (const float*)d_in[2];
    const float* as1 = (const float*)d_in[3];
    const float* ad1 = (const float*)d_in[4];
    const float* b1  = (const float*)d_in[5];
    const float* W2  = (const float*)d_in[6];
    const float* as2 = (const float*)d_in[7];
    const float* ad2 = (const float*)d_in[8];
    const float* b2  = (const float*)d_in[9];
    float* out = (float*)d_out;

    float *g_h_p, *pas1, *pad1, *pas2, *pad2;
    cudaGetSymbolAddress((void**)&g_h_p, g_h);
    cudaGetSymbolAddress((void**)&pas1, g_as1);
    cudaGetSymbolAddress((void**)&pad1, g_ad1);
    cudaGetSymbolAddress((void**)&pas2, g_as2);
    cudaGetSymbolAddress((void**)&pad2, g_ad2);
    __nv_bfloat16 *thi, *tlo, *w1hi, *w1lo, *w2hi, *w2lo;
    cudaGetSymbolAddress((void**)&thi, g_thi);   cudaGetSymbolAddress((void**)&tlo, g_tlo);
    cudaGetSymbolAddress((void**)&w1hi, g_w1hi); cudaGetSymbolAddress((void**)&w1lo, g_w1lo);
    cudaGetSymbolAddress((void**)&w2hi, g_w2hi); cudaGetSymbolAddress((void**)&w2lo, g_w2lo);

    constexpr int SMEM64 = 2 * (2 * ABYTES + 2 * (64 * KPAD * 2));   // 61440

    // one-time host objects (no device memory involved)
    static cudaStream_t sCSR = nullptr;
    static cudaEvent_t evFork = nullptr, evCSR = nullptr;
    if (sCSR == nullptr) {
        cudaFuncSetAttribute(gemm_mma_kernel<CHID, 64, true>,
                             cudaFuncAttributeMaxDynamicSharedMemorySize, SMEM64);
        cudaFuncSetAttribute(gemm_mma_kernel<COUT, 64, false>,
                             cudaFuncAttributeMaxDynamicSharedMemorySize, SMEM64);
        cudaStreamCreateWithFlags(&sCSR, cudaStreamNonBlocking);
        cudaEventCreateWithFlags(&evFork, cudaEventDisableTiming);
        cudaEventCreateWithFlags(&evCSR, cudaEventDisableTiming);
    }

    const int TPB = 256;
    const int nblk_edges = (ETOT + TPB - 1) / TPB;
    const int MTILES = (NNODES + 127) / 128;   // 157

    // PDL launch config (chained: setup -> gemm1 -> agg1 -> gemm2 -> agg2)
    cudaLaunchAttribute pdlAttr[1];
    pdlAttr[0].id = cudaLaunchAttributeProgrammaticStreamSerialization;
    pdlAttr[0].val.programmaticStreamSerializationAllowed = 1;

    // ---- stream 0: setup (init + detect + weight conversion) ----
    setup_kernel<<<NBLK_N + NBLK_W, TPB>>>(ei, W1, W2);
    cudaEventRecord(evFork, 0);

    // ---- CSR branch (sCSR) ----
    cudaStreamWaitEvent(sCSR, evFork, 0);
    convert_count_kernel<<<nblk_edges, TPB, 0, sCSR>>>(ei);
    scan_part_kernel<<<NBLK_N, 256, 0, sCSR>>>();
    scan_write_kernel<<<NBLK_N, 256, 0, sCSR>>>();
    fill_kernel<<<nblk_edges, TPB, 0, sCSR>>>();
    cudaEventRecord(evCSR, sCSR);

    // ---- main: GEMM1 (PDL after setup; fp32 x, fused bf16 split) ----
    {
        cudaLaunchConfig_t cfg = {};
        cfg.gridDim = dim3(CHID / 64, MTILES);
        cfg.blockDim = dim3(256, 1, 1);
        cfg.dynamicSmemBytes = SMEM64;
        cfg.stream = 0;
        cfg.attrs = pdlAttr;
        cfg.numAttrs = 1;
        int M = NNODES, K = CIN;
        cudaLaunchKernelEx(&cfg, gemm_mma_kernel<CHID, 64, true>,
                           (const void*)x, (const __nv_bfloat16*)nullptr,
                           (const __nv_bfloat16*)w1hi, (const __nv_bfloat16*)w1lo,
                           (float*)g_h_p, (const float*)as1, (const float*)ad1,
                           (float*)pas1, (float*)pad1, M, K);
    }

    // ---- join CSR, aggregate1 (PDL after gemm1; CSR via hard event edge) ----
    cudaStreamWaitEvent(0, evCSR, 0);
    {
        cudaLaunchConfig_t cfg = {};
        cfg.gridDim = dim3(NNODES, 1, 1);
        cfg.blockDim = dim3(CHID / 4, 1, 1);
        cfg.dynamicSmemBytes = 0;
        cfg.stream = 0;
        cfg.attrs = pdlAttr;
        cfg.numAttrs = 1;
        cudaLaunchKernelEx(&cfg, aggregate_kernel<CHID, true>,
                           (const float*)g_h_p, (const float*)b1,
                           (const float*)pas1, (const float*)pad1, (float*)nullptr);
    }

    // ---- layer 2 (PDL chained: agg1 -> gemm2 -> agg2) ----
    {
        cudaLaunchConfig_t cfg = {};
        cfg.gridDim = dim3(COUT / 64, MTILES);
        cfg.blockDim = dim3(256, 1, 1);
        cfg.dynamicSmemBytes = SMEM64;
        cfg.stream = 0;
        cfg.attrs = pdlAttr;
        cfg.numAttrs = 1;
        int M = NNODES, K = CHID;
        cudaLaunchKernelEx(&cfg, gemm_mma_kernel<COUT, 64, false>,
                           (const void*)thi, (const __nv_bfloat16*)tlo,
                           (const __nv_bfloat16*)w2hi, (const __nv_bfloat16*)w2lo,
                           (float*)g_h_p, (const float*)as2, (const float*)ad2,
                           (float*)pas2, (float*)pad2, M, K);
    }
    {
        cudaLaunchConfig_t cfg = {};
        cfg.gridDim = dim3(NNODES, 1, 1);
        cfg.blockDim = dim3(COUT / 4, 1, 1);
        cfg.dynamicSmemBytes = 0;
        cfg.stream = 0;
        cfg.attrs = pdlAttr;
        cfg.numAttrs = 1;
        cudaLaunchKernelEx(&cfg, aggregate_kernel<COUT, false>,
                           (const float*)g_h_p, (const float*)b2,
                           (const float*)pas2, (const float*)pad2, (float*)out);
    }
}

// round 16
// speedup vs baseline: 1.4204x; 1.0132x over previous
#include <cuda_runtime.h>
#include <cuda_bf16.h>
#include <cuda_fp16.h>
#include <math_constants.h>
#include <cstdint>

// ---------------- problem constants ----------------
#define NNODES 20000
#define NEDGES 320000
#define ETOT   (NEDGES + NNODES)   // + self loops
#define CIN    256
#define CHID   256
#define COUT   128
#define NEG_SLOPE 0.2f
#define NBLK_N ((NNODES + 255) / 256)   // 79
#define CONVW_ELEMS (CIN * CHID + CHID * COUT)          // 98304
#define NBLK_W ((CONVW_ELEMS + 255) / 256)              // 384

// ---------------- device scratch (no allocations allowed) ----------------
__device__ __half g_hh[NNODES * CHID];   // GEMM output, fp16 (halves agg traffic,
                                         // 10-bit mantissa keeps rel_err ~1e-4)
__device__ float g_as1[NNODES];
__device__ float g_ad1[NNODES];
__device__ float g_as2[NNODES];
__device__ float g_ad2[NNODES];
__device__ int   g_deg[NNODES];
__device__ int   g_bsum[NBLK_N];
__device__ int   g_off[NNODES + 1];
__device__ int   g_cur[NNODES];
__device__ int   g_srcs[ETOT];
__device__ int   g_esrc[ETOT];
__device__ int   g_edst[ETOT];
__device__ int   g_is64;

// bf16 split operands (weights + layer-2 activations; x converts inside GEMM1)
__device__ __nv_bfloat16 g_thi[NNODES * CHID];   // layer-2 input (written by aggregate1)
__device__ __nv_bfloat16 g_tlo[NNODES * CHID];
__device__ __nv_bfloat16 g_w1hi[CHID * CIN];     // W1^T : [N=CHID][K=CIN]
__device__ __nv_bfloat16 g_w1lo[CHID * CIN];
__device__ __nv_bfloat16 g_w2hi[COUT * CHID];    // W2^T : [N=COUT][K=CHID]
__device__ __nv_bfloat16 g_w2lo[COUT * CHID];

// ---------------- PDL helpers (no-ops when not PDL-launched) ----------------
__device__ __forceinline__ void pdl_trigger() {
    asm volatile("griddepcontrol.launch_dependents;" ::: "memory");
}
__device__ __forceinline__ void pdl_wait() {
    asm volatile("griddepcontrol.wait;" ::: "memory");
}

// ---------------- split / pack helpers ----------------
__device__ __forceinline__ void bf16_split(float v, __nv_bfloat16& hi, __nv_bfloat16& lo) {
    hi = __float2bfloat16(v);
    lo = __float2bfloat16(v - __bfloat162float(hi));
}
__device__ __forceinline__ void split_pair(float v0, float v1,
                                           uint32_t& hw, uint32_t& lw) {
    __nv_bfloat16 h0, l0, h1, l1;
    bf16_split(v0, h0, l0);
    bf16_split(v1, h1, l1);
    hw = ((uint32_t)__bfloat16_as_ushort(h1) << 16) | __bfloat16_as_ushort(h0);
    lw = ((uint32_t)__bfloat16_as_ushort(l1) << 16) | __bfloat16_as_ushort(l0);
}
// pack (v0 -> low 16, v1 -> high 16) fp16, round-to-nearest
__device__ __forceinline__ uint32_t pack_f16x2(float v0, float v1) {
    __half2 p = __floats2half2_rn(v0, v1);   // .x = v0 (low), .y = v1 (high)
    return *reinterpret_cast<uint32_t*>(&p);
}
__device__ __forceinline__ float2 unpack_f16x2(uint32_t w) {
    __half2 p = *reinterpret_cast<__half2*>(&w);
    return __half22float2(p);
}

// ---------------- setup: detect dtype + zero init + weight conversion ----------------
__global__ void setup_kernel(const void* __restrict__ ei,
                             const float* __restrict__ W1,
                             const float* __restrict__ W2) {
    const int b = blockIdx.x;
    if (b < NBLK_N) {
        int i = b * blockDim.x + threadIdx.x;
        if (i < NNODES) {
            g_deg[i] = 0;
            g_as1[i] = 0.f; g_ad1[i] = 0.f;
            g_as2[i] = 0.f; g_ad2[i] = 0.f;
        }
        if (b == 0) {
            const long long* p = (const long long*)ei;
            int bad = 0;
            #pragma unroll
            for (int k = threadIdx.x; k < 2048; k += 256) {
                long long v = p[k];
                if (v < 0 || v >= NNODES) bad = 1;
            }
            int anybad = __syncthreads_or(bad);
            if (threadIdx.x == 0) g_is64 = !anybad;
        }
    } else {
        int i = (b - NBLK_N) * blockDim.x + threadIdx.x;
        if (i < CIN * CHID) {
            int k = i / CHID, n = i % CHID;           // W1[k][n] -> w1t[n][k]
            bf16_split(W1[i], g_w1hi[n * CIN + k], g_w1lo[n * CIN + k]);
        } else if (i < CONVW_ELEMS) {
            int j = i - CIN * CHID;
            int k = j / COUT, n = j % COUT;           // W2[k][n] -> w2t[n][k]
            bf16_split(W2[j], g_w2hi[n * CHID + k], g_w2lo[n * CHID + k]);
        }
    }
    pdl_trigger();   // dependent (GEMM1) may begin launching; it pdl_waits before reads
}

// ---------------- convert + degree count ----------------
__global__ void convert_count_kernel(const void* __restrict__ ei) {
    int e = blockIdx.x * blockDim.x + threadIdx.x;
    if (e >= ETOT) return;
    int s, d;
    if (e < NEDGES) {
        if (g_is64) {
            const long long* p = (const long long*)ei;
            s = (int)p[e]; d = (int)p[NEDGES + e];
        } else {
            const int* p = (const int*)ei;
            s = p[e]; d = p[NEDGES + e];
        }
    } else {
        s = e - NEDGES; d = s;
    }
    g_esrc[e] = s;
    g_edst[e] = d;
    atomicAdd(&g_deg[d], 1);
}

// ---------------- multi-block scan ----------------
__global__ void scan_part_kernel() {
    __shared__ int sh[256];
    int i = blockIdx.x * 256 + threadIdx.x;
    sh[threadIdx.x] = (i < NNODES) ? g_deg[i] : 0;
    __syncthreads();
    #pragma unroll
    for (int st = 128; st > 0; st >>= 1) {
        if (threadIdx.x < st) sh[threadIdx.x] += sh[threadIdx.x + st];
        __syncthreads();
    }
    if (threadIdx.x == 0) g_bsum[blockIdx.x] = sh[0];
}

__global__ void scan_write_kernel() {
    __shared__ int sh[256];
    __shared__ int base_sh;
    const int t = threadIdx.x;
    const int b = blockIdx.x;
    int pv = (t < b && t < NBLK_N) ? g_bsum[t] : 0;
    sh[t] = pv;
    __syncthreads();
    #pragma unroll
    for (int st = 128; st > 0; st >>= 1) {
        if (t < st) sh[t] += sh[t + st];
        __syncthreads();
    }
    if (t == 0) base_sh = sh[0];
    __syncthreads();
    const int base = base_sh;
    __syncthreads();
    int i = b * 256 + t;
    int d = (i < NNODES) ? g_deg[i] : 0;
    sh[t] = d;
    __syncthreads();
    #pragma unroll
    for (int st = 1; st < 256; st <<= 1) {
        int v = (t >= st) ? sh[t - st] : 0;
        __syncthreads();
        sh[t] += v;
        __syncthreads();
    }
    if (i < NNODES) {
        int off = base + sh[t] - d;
        g_off[i] = off;
        g_cur[i] = off;
    }
    if (b == NBLK_N - 1 && t == 255) g_off[NNODES] = base + sh[255];
}

__global__ void fill_kernel() {
    int e = blockIdx.x * blockDim.x + threadIdx.x;
    if (e >= ETOT) return;
    int pos = atomicAdd(&g_cur[g_edst[e]], 1);
    g_srcs[pos] = g_esrc[e];
}

// ---------------- bf16-split warp MMA GEMM ----------------
// C[M x NC] = (Ahi+Alo)[M x K] @ ((Bhi+Blo)[NC x K])^T, 3 combos, fp32 accum.
// CTA tile 128 x BN, 8 warps (4 m x 2 n), warp tile 32 x BN/2, mma m16n8k16.
// AFP32: A arrives as fp32 and is split to bf16 hi/lo in-register (fused conv).
// Epilogue: fp32 alpha dots (exact) + h stored as packed fp16x2 (halved traffic).
#define KC    32
#define KPAD  40                          // 80B row stride, conflict-free fragments
#define ABYTES (128 * KPAD * 2)           // 10240

__device__ __forceinline__ void mma16816(float* c, const uint32_t* a, const uint32_t* b) {
    asm volatile(
        "mma.sync.aligned.m16n8k16.row.col.f32.bf16.bf16.f32 "
        "{%0,%1,%2,%3}, {%4,%5,%6,%7}, {%8,%9}, {%0,%1,%2,%3};"
        : "+f"(c[0]), "+f"(c[1]), "+f"(c[2]), "+f"(c[3])
        : "r"(a[0]), "r"(a[1]), "r"(a[2]), "r"(a[3]), "r"(b[0]), "r"(b[1]));
}

__device__ __forceinline__ uint32_t smem_u32(const void* p) {
    uint32_t a;
    asm("{ .reg .u64 t; cvta.to.shared.u64 t, %1; cvt.u32.u64 %0, t; }" : "=r"(a) : "l"(p));
    return a;
}
__device__ __forceinline__ void cp16(uint32_t dst, const void* src) {
    asm volatile("cp.async.cg.shared.global [%0], [%1], 16;" :: "r"(dst), "l"(src));
}

template <int NC, int BN, bool AFP32>
__global__ __launch_bounds__(256)
void gemm_mma_kernel(const void* __restrict__ Aarg, const __nv_bfloat16* __restrict__ Alo,
                     const __nv_bfloat16* __restrict__ Bhi, const __nv_bfloat16* __restrict__ Blo,
                     __half* __restrict__ Ch,
                     const float* __restrict__ avs, const float* __restrict__ avd,
                     float* __restrict__ as_out, float* __restrict__ ad_out,
                     int M, int K) {
    constexpr int NT      = BN / 16;            // n-tiles per warp
    constexpr int BBYTES  = BN * KPAD * 2;
    constexpr int BUFB    = 2 * ABYTES + 2 * BBYTES;

    extern __shared__ char smem[];
    const uint32_t sb = smem_u32(smem);

    const int tid   = threadIdx.x;
    const int wid   = tid >> 5;
    const int lane  = tid & 31;
    const int wm    = wid & 3;
    const int wn    = wid >> 2;
    const int g     = lane >> 2;
    const int t     = lane & 3;
    const int m0    = blockIdx.y * 128;
    const int n0    = blockIdx.x * BN;

    const float* Af = (const float*)Aarg;
    const __nv_bfloat16* Ahi = (const __nv_bfloat16*)Aarg;

    pdl_trigger();          // let dependent kernel launch early
    pdl_wait();             // inputs may come from the immediately preceding kernel

    float acc[2][NT][4];
    #pragma unroll
    for (int i = 0; i < 2; i++)
        #pragma unroll
        for (int j = 0; j < NT; j++)
            #pragma unroll
            for (int q = 0; q < 4; q++) acc[i][j][q] = 0.0f;

    const int NCHUNK = K / KC;

    // fused-conversion A staging (AFP32): one thread = 16 contiguous fp32
    const int arowA = min(m0 + (tid >> 1), M - 1);
    const int halfA = tid & 1;
    float areg[AFP32 ? 16 : 1];

    auto ldgA = [&](int ch) {
        if constexpr (AFP32) {
            const float* p = Af + (size_t)arowA * K + ch * KC + halfA * 16;
            #pragma unroll
            for (int v = 0; v < 4; v++)
                *reinterpret_cast<float4*>(&areg[4 * v]) =
                    *reinterpret_cast<const float4*>(p + 4 * v);
        }
    };
    auto stsA = [&](int buf) {
        if constexpr (AFP32) {
            uint32_t hw[8], lw[8];
            #pragma unroll
            for (int i = 0; i < 8; i++)
                split_pair(areg[2 * i], areg[2 * i + 1], hw[i], lw[i]);
            char* base = smem + buf * BUFB + (tid >> 1) * (KPAD * 2) + halfA * 32;
            *reinterpret_cast<uint4*>(base)      = make_uint4(hw[0], hw[1], hw[2], hw[3]);
            *reinterpret_cast<uint4*>(base + 16) = make_uint4(hw[4], hw[5], hw[6], hw[7]);
            char* lbase = base + ABYTES;
            *reinterpret_cast<uint4*>(lbase)      = make_uint4(lw[0], lw[1], lw[2], lw[3]);
            *reinterpret_cast<uint4*>(lbase + 16) = make_uint4(lw[4], lw[5], lw[6], lw[7]);
        }
    };

    auto issue_chunk = [&](int ch, int buf) {
        const int kc0 = ch * KC;
        const uint32_t bbase = sb + buf * BUFB;
        if constexpr (!AFP32) {
            #pragma unroll
            for (int it = 0; it < 2; it++) {                // A: 128 rows x 4 slots
                const int idx = tid + it * 256;
                const int row = idx >> 2;
                const int c4  = idx & 3;
                const int arow = min(m0 + row, M - 1);      // clamp; garbage rows unsaved
                const size_t ao = (size_t)arow * K + kc0 + c4 * 8;
                const uint32_t so = (uint32_t)(row * (KPAD * 2) + c4 * 16);
                cp16(bbase + so, Ahi + ao);
                cp16(bbase + ABYTES + so, Alo + ao);
            }
        }
        #pragma unroll
        for (int it = 0; it < BN * 4 / 256; it++) {         // B: BN rows x 4 slots
            const int idx = tid + it * 256;
            const int row = idx >> 2;
            const int c4  = idx & 3;
            const size_t bo = (size_t)(n0 + row) * K + kc0 + c4 * 8;  // NC mult of BN
            const uint32_t so = (uint32_t)(row * (KPAD * 2) + c4 * 16);
            cp16(bbase + 2 * ABYTES + so, Bhi + bo);
            cp16(bbase + 2 * ABYTES + BBYTES + so, Blo + bo);
        }
        asm volatile("cp.async.commit_group;" ::: "memory");
    };

    // prologue
    ldgA(0);
    issue_chunk(0, 0);
    stsA(0);

    for (int ch = 0; ch < NCHUNK; ch++) {
        const int buf = ch & 1;
        const bool more = (ch + 1 < NCHUNK);
        if (more) {
            ldgA(ch + 1);
            issue_chunk(ch + 1, buf ^ 1);
        }
        if (more) asm volatile("cp.async.wait_group 1;" ::: "memory");
        else      asm volatile("cp.async.wait_group 0;" ::: "memory");
        __syncthreads();

        const char* pbuf = smem + buf * BUFB;
        #pragma unroll
        for (int ks = 0; ks < KC / 16; ks++) {
            const int kb = ks * 16;
            #pragma unroll
            for (int combo = 0; combo < 3; combo++) {
                const char* pA = pbuf + ((combo == 2) ? ABYTES : 0);
                const char* pB = pbuf + 2 * ABYTES + ((combo == 1) ? BBYTES : 0);

                uint32_t afrag[2][4];
                #pragma unroll
                for (int mt = 0; mt < 2; mt++) {
                    const int r0 = wm * 32 + mt * 16 + g;
                    const char* q0 = pA + r0 * (KPAD * 2) + (kb + 2 * t) * 2;
                    const char* q1 = pA + (r0 + 8) * (KPAD * 2) + (kb + 2 * t) * 2;
                    afrag[mt][0] = *reinterpret_cast<const uint32_t*>(q0);
                    afrag[mt][1] = *reinterpret_cast<const uint32_t*>(q1);
                    afrag[mt][2] = *reinterpret_cast<const uint32_t*>(q0 + 16);
                    afrag[mt][3] = *reinterpret_cast<const uint32_t*>(q1 + 16);
                }
                uint32_t bfrag[NT][2];
                #pragma unroll
                for (int nt = 0; nt < NT; nt++) {
                    const int n = wn * (BN / 2) + nt * 8 + g;
                    const char* q = pB + n * (KPAD * 2) + (kb + 2 * t) * 2;
                    bfrag[nt][0] = *reinterpret_cast<const uint32_t*>(q);
                    bfrag[nt][1] = *reinterpret_cast<const uint32_t*>(q + 16);
                }
                #pragma unroll
                for (int mt = 0; mt < 2; mt++)
                    #pragma unroll
                    for (int nt = 0; nt < NT; nt++)
                        mma16816(acc[mt][nt], afrag[mt], bfrag[nt]);
            }
        }
        if (more) stsA(buf ^ 1);   // visible after next iteration's __syncthreads
        __syncthreads();           // buf free for reuse
    }

    // ---- epilogue: fp16x2 store of h + fused fp32 alpha dots (exact) ----
    float sa[4] = {0.f, 0.f, 0.f, 0.f};   // rows: wm*32 + {0,8,16,24} + g
    float da[4] = {0.f, 0.f, 0.f, 0.f};
    #pragma unroll
    for (int mt = 0; mt < 2; mt++) {
        const int r0 = m0 + wm * 32 + mt * 16 + g;
        #pragma unroll
        for (int nt = 0; nt < NT; nt++) {
            const int col = n0 + wn * (BN / 2) + nt * 8 + 2 * t;
            const float v0 = avs[col], v1 = avs[col + 1];
            const float u0 = avd[col], u1 = avd[col + 1];
            sa[2 * mt]     += acc[mt][nt][0] * v0 + acc[mt][nt][1] * v1;
            da[2 * mt]     += acc[mt][nt][0] * u0 + acc[mt][nt][1] * u1;
            sa[2 * mt + 1] += acc[mt][nt][2] * v0 + acc[mt][nt][3] * v1;
            da[2 * mt + 1] += acc[mt][nt][2] * u0 + acc[mt][nt][3] * u1;
            if (r0 < M)
                *reinterpret_cast<uint32_t*>(&Ch[(size_t)r0 * NC + col]) =
                    pack_f16x2(acc[mt][nt][0], acc[mt][nt][1]);
            if (r0 + 8 < M)
                *reinterpret_cast<uint32_t*>(&Ch[(size_t)(r0 + 8) * NC + col]) =
                    pack_f16x2(acc[mt][nt][2], acc[mt][nt][3]);
        }
    }
    #pragma unroll
    for (int q = 0; q < 4; q++) {
        sa[q] += __shfl_xor_sync(0xffffffffu, sa[q], 1);
        sa[q] += __shfl_xor_sync(0xffffffffu, sa[q], 2);
        da[q] += __shfl_xor_sync(0xffffffffu, da[q], 1);
        da[q] += __shfl_xor_sync(0xffffffffu, da[q], 2);
    }
    if (t == 0) {
        #pragma unroll
        for (int q = 0; q < 4; q++) {
            const int r = m0 + wm * 32 + q * 8 + g;
            if (r < M) {
                atomicAdd(&as_out[r], sa[q]);
                atomicAdd(&ad_out[r], da[q]);
            }
        }
    }
}

// ---------------- fused softmax + aggregation: one block per dst, fp16 gather ----------------
// blockDim = C/4; each thread owns 4 channels, gathers one uint2 (4 x fp16) per edge
// (half the L2 traffic of fp32). Accumulation in fp32. 2-way unrolled.
// No max-subtraction: logits ~ N(0, sqrt(2)); exp is overflow-safe and the
// softmax ratio is mathematically identical.
template <int C, bool BF16OUT>
__global__ void aggregate_kernel(const __half* __restrict__ hh,
                                 const float* __restrict__ bias,
                                 const float* __restrict__ as_in,
                                 const float* __restrict__ ad_in,
                                 float* __restrict__ out) {
    constexpr int TH = C / 4;
    __shared__ float ws[TH];
    __shared__ int   ss[TH];
    const int d   = blockIdx.x;
    const int tid = threadIdx.x;

    pdl_trigger();
    // PDL prologue: CSR data (g_off/g_srcs) is guaranteed by the event edge,
    // not by the immediately preceding kernel, so stage it before pdl_wait.
    const int beg = g_off[d];
    const int end = g_off[d + 1];
    float ad = 0.0f;
    bool waited = false;

    float4 acc0 = make_float4(0.f, 0.f, 0.f, 0.f);
    float4 acc1 = make_float4(0.f, 0.f, 0.f, 0.f);
    float den0 = 0.0f, den1 = 0.0f;
    for (int cbeg = beg; cbeg < end; cbeg += TH) {
        const int nchunk = min(TH, end - cbeg);
        __syncthreads();
        int s = -1;
        if (tid < nchunk) {
            s = g_srcs[cbeg + tid];
            ss[tid] = s;
        }
        if (!waited) {           // first iteration: wait for h / as / ad producers
            pdl_wait();
            ad = ad_in[d];
            waited = true;
        }
        if (tid < nchunk) {
            float tt = as_in[s] + ad;
            float l = tt > 0.0f ? tt : NEG_SLOPE * tt;
            ws[tid] = __expf(l);
        }
        __syncthreads();
        int jj = 0;
        for (; jj + 2 <= nchunk; jj += 2) {
            const float w0 = ws[jj];
            const float w1 = ws[jj + 1];
            const uint2 p0 = *reinterpret_cast<const uint2*>(
                &hh[(size_t)ss[jj] * C + 4 * tid]);
            const uint2 p1 = *reinterpret_cast<const uint2*>(
                &hh[(size_t)ss[jj + 1] * C + 4 * tid]);
            const float2 a01 = unpack_f16x2(p0.x), a23 = unpack_f16x2(p0.y);
            const float2 b01 = unpack_f16x2(p1.x), b23 = unpack_f16x2(p1.y);
            den0 += w0; den1 += w1;
            acc0.x += w0 * a01.x;  acc1.x += w1 * b01.x;
            acc0.y += w0 * a01.y;  acc1.y += w1 * b01.y;
            acc0.z += w0 * a23.x;  acc1.z += w1 * b23.x;
            acc0.w += w0 * a23.y;  acc1.w += w1 * b23.y;
        }
        if (jj < nchunk) {
            const float w = ws[jj];
            const uint2 p = *reinterpret_cast<const uint2*>(
                &hh[(size_t)ss[jj] * C + 4 * tid]);
            const float2 a01 = unpack_f16x2(p.x), a23 = unpack_f16x2(p.y);
            den0 += w;
            acc0.x += w * a01.x; acc0.y += w * a01.y;
            acc0.z += w * a23.x; acc0.w += w * a23.y;
        }
    }

    const float inv = 1.0f / (den0 + den1);
    const float4 bv = *reinterpret_cast<const float4*>(&bias[4 * tid]);
    float4 r;
    r.x = (acc0.x + acc1.x) * inv + bv.x;
    r.y = (acc0.y + acc1.y) * inv + bv.y;
    r.z = (acc0.z + acc1.z) * inv + bv.z;
    r.w = (acc0.w + acc1.w) * inv + bv.w;
    if (BF16OUT) {
        r.x = fmaxf(r.x, 0.f); r.y = fmaxf(r.y, 0.f);
        r.z = fmaxf(r.z, 0.f); r.w = fmaxf(r.w, 0.f);
        uint32_t h01, l01, h23, l23;
        split_pair(r.x, r.y, h01, l01);
        split_pair(r.z, r.w, h23, l23);
        *reinterpret_cast<uint2*>(&g_thi[(size_t)d * C + 4 * tid]) = make_uint2(h01, h23);
        *reinterpret_cast<uint2*>(&g_tlo[(size_t)d * C + 4 * tid]) = make_uint2(l01, l23);
    } else {
        *reinterpret_cast<float4*>(&out[(size_t)d * C + 4 * tid]) = r;
    }
}

// ---------------- launch ----------------
extern "C" void kernel_launch(void* const* d_in, const int* in_sizes, int n_in,
                              void* d_out, int out_size) {
    const float* x   = (const float*)d_in[0];
    const void*  ei  = (const void*)d_in[1];
    const float* W1  = (const float*)d_in[2];
    const float* as1 = (const float*)d_in[3];
    const float* ad1 = (const float*)d_in[4];
    const float* b1  = (const float*)d_in[5];
    const float* W2  = (const float*)d_in[6];
    const float* as2 = (const float*)d_in[7];
    const float* ad2 = (const float*)d_in[8];
    const float* b2  = (const float*)d_in[9];
    float* out = (float*)d_out;

    float *pas1, *pad1, *pas2, *pad2;
    cudaGetSymbolAddress((void**)&pas1, g_as1);
    cudaGetSymbolAddress((void**)&pad1, g_ad1);
    cudaGetSymbolAddress((void**)&pas2, g_as2);
    cudaGetSymbolAddress((void**)&pad2, g_ad2);
    __half* hh;
    cudaGetSymbolAddress((void**)&hh, g_hh);
    __nv_bfloat16 *thi, *tlo, *w1hi, *w1lo, *w2hi, *w2lo;
    cudaGetSymbolAddress((void**)&thi, g_thi);   cudaGetSymbolAddress((void**)&tlo, g_tlo);
    cudaGetSymbolAddress((void**)&w1hi, g_w1hi); cudaGetSymbolAddress((void**)&w1lo, g_w1lo);
    cudaGetSymbolAddress((void**)&w2hi, g_w2hi); cudaGetSymbolAddress((void**)&w2lo, g_w2lo);

    constexpr int SMEM64 = 2 * (2 * ABYTES + 2 * (64 * KPAD * 2));   // 61440

    // one-time host objects (no device memory involved)
    static cudaStream_t sCSR = nullptr;
    static cudaEvent_t evFork = nullptr, evCSR = nullptr;
    if (sCSR == nullptr) {
        cudaFuncSetAttribute(gemm_mma_kernel<CHID, 64, true>,
                             cudaFuncAttributeMaxDynamicSharedMemorySize, SMEM64);
        cudaFuncSetAttribute(gemm_mma_kernel<COUT, 64, false>,
                             cudaFuncAttributeMaxDynamicSharedMemorySize, SMEM64);
        cudaStreamCreateWithFlags(&sCSR, cudaStreamNonBlocking);
        cudaEventCreateWithFlags(&evFork, cudaEventDisableTiming);
        cudaEventCreateWithFlags(&evCSR, cudaEventDisableTiming);
    }

    const int TPB = 256;
    const int nblk_edges = (ETOT + TPB - 1) / TPB;
    const int MTILES = (NNODES + 127) / 128;   // 157

    // PDL launch config (chained: setup -> gemm1 -> agg1 -> gemm2 -> agg2)
    cudaLaunchAttribute pdlAttr[1];
    pdlAttr[0].id = cudaLaunchAttributeProgrammaticStreamSerialization;
    pdlAttr[0].val.programmaticStreamSerializationAllowed = 1;

    // ---- stream 0: setup (init + detect + weight conversion) ----
    setup_kernel<<<NBLK_N + NBLK_W, TPB>>>(ei, W1, W2);
    cudaEventRecord(evFork, 0);

    // ---- CSR branch (sCSR) ----
    cudaStreamWaitEvent(sCSR, evFork, 0);
    convert_count_kernel<<<nblk_edges, TPB, 0, sCSR>>>(ei);
    scan_part_kernel<<<NBLK_N, 256, 0, sCSR>>>();
    scan_write_kernel<<<NBLK_N, 256, 0, sCSR>>>();
    fill_kernel<<<nblk_edges, TPB, 0, sCSR>>>();
    cudaEventRecord(evCSR, sCSR);

    // ---- main: GEMM1 (PDL after setup; fp32 x, fused bf16 split) ----
    {
        cudaLaunchConfig_t cfg = {};
        cfg.gridDim = dim3(CHID / 64, MTILES);
        cfg.blockDim = dim3(256, 1, 1);
        cfg.dynamicSmemBytes = SMEM64;
        cfg.stream = 0;
        cfg.attrs = pdlAttr;
        cfg.numAttrs = 1;
        int M = NNODES, K = CIN;
        cudaLaunchKernelEx(&cfg, gemm_mma_kernel<CHID, 64, true>,
                           (const void*)x, (const __nv_bfloat16*)nullptr,
                           (const __nv_bfloat16*)w1hi, (const __nv_bfloat16*)w1lo,
                           (__half*)hh, (const float*)as1, (const float*)ad1,
                           (float*)pas1, (float*)pad1, M, K);
    }

    // ---- join CSR, aggregate1 (PDL after gemm1; CSR via hard event edge) ----
    cudaStreamWaitEvent(0, evCSR, 0);
    {
        cudaLaunchConfig_t cfg = {};
        cfg.gridDim = dim3(NNODES, 1, 1);
        cfg.blockDim = dim3(CHID / 4, 1, 1);
        cfg.dynamicSmemBytes = 0;
        cfg.stream = 0;
        cfg.attrs = pdlAttr;
        cfg.numAttrs = 1;
        cudaLaunchKernelEx(&cfg, aggregate_kernel<CHID, true>,
                           (const __half*)hh, (const float*)b1,
                           (const float*)pas1, (const float*)pad1, (float*)nullptr);
    }

    // ---- layer 2 (PDL chained: agg1 -> gemm2 -> agg2) ----
    {
        cudaLaunchConfig_t cfg = {};
        cfg.gridDim = dim3(COUT / 64, MTILES);
        cfg.blockDim = dim3(256, 1, 1);
        cfg.dynamicSmemBytes = SMEM64;
        cfg.stream = 0;
        cfg.attrs = pdlAttr;
        cfg.numAttrs = 1;
        int M = NNODES, K = CHID;
        cudaLaunchKernelEx(&cfg, gemm_mma_kernel<COUT, 64, false>,
                           (const void*)thi, (const __nv_bfloat16*)tlo,
                           (const __nv_bfloat16*)w2hi, (const __nv_bfloat16*)w2lo,
                           (__half*)hh, (const float*)as2, (const float*)ad2,
                           (float*)pas2, (float*)pad2, M, K);
    }
    {
        cudaLaunchConfig_t cfg = {};
        cfg.gridDim = dim3(NNODES, 1, 1);
        cfg.blockDim = dim3(COUT / 4, 1, 1);
        cfg.dynamicSmemBytes = 0;
        cfg.stream = 0;
        cfg.attrs = pdlAttr;
        cfg.numAttrs = 1;
        cudaLaunchKernelEx(&cfg, aggregate_kernel<COUT, false>,
                           (const __half*)hh, (const float*)b2,
                           (const float*)pas2, (const float*)pad2, (float*)out);
    }
}

// round 17
// speedup vs baseline: 1.6077x; 1.1319x over previous
#include <cuda_runtime.h>
#include <cuda_fp16.h>
#include <math_constants.h>
#include <cstdint>

// ---------------- problem constants ----------------
#define NNODES 20000
#define NEDGES 320000
#define ETOT   (NEDGES + NNODES)   // + self loops
#define CIN    256
#define CHID   256
#define COUT   128
#define NEG_SLOPE 0.2f
#define NBLK_N ((NNODES + 255) / 256)   // 79
#define CONVW_ELEMS (CIN * CHID + CHID * COUT)          // 98304
#define NBLK_W ((CONVW_ELEMS + 255) / 256)              // 384

// ---------------- device scratch (no allocations allowed) ----------------
__device__ __half g_hh[NNODES * CHID];   // GEMM output, fp16
__device__ __half g_t[NNODES * CHID];    // layer-2 input, fp16 (written by aggregate1)
__device__ __half g_w1h[CHID * CIN];     // W1^T fp16 : [N=CHID][K=CIN]
__device__ __half g_w2h[COUT * CHID];    // W2^T fp16 : [N=COUT][K=CHID]
__device__ float g_as1[NNODES];
__device__ float g_ad1[NNODES];
__device__ float g_as2[NNODES];
__device__ float g_ad2[NNODES];
__device__ int   g_deg[NNODES];
__device__ int   g_bsum[NBLK_N];
__device__ int   g_off[NNODES + 1];
__device__ int   g_cur[NNODES];
__device__ int   g_srcs[ETOT];
__device__ int   g_esrc[ETOT];
__device__ int   g_edst[ETOT];
__device__ int   g_is64;

// ---------------- PDL helpers (no-ops when not PDL-launched) ----------------
__device__ __forceinline__ void pdl_trigger() {
    asm volatile("griddepcontrol.launch_dependents;" ::: "memory");
}
__device__ __forceinline__ void pdl_wait() {
    asm volatile("griddepcontrol.wait;" ::: "memory");
}

// ---------------- pack helpers ----------------
__device__ __forceinline__ uint32_t pack_f16x2(float v0, float v1) {
    __half2 p = __floats2half2_rn(v0, v1);
    return *reinterpret_cast<uint32_t*>(&p);
}
__device__ __forceinline__ float2 unpack_f16x2(uint32_t w) {
    __half2 p = *reinterpret_cast<__half2*>(&w);
    return __half22float2(p);
}

// ---------------- setup: detect dtype + zero init + weight conversion ----------------
__global__ void setup_kernel(const void* __restrict__ ei,
                             const float* __restrict__ W1,
                             const float* __restrict__ W2) {
    const int b = blockIdx.x;
    if (b < NBLK_N) {
        int i = b * blockDim.x + threadIdx.x;
        if (i < NNODES) {
            g_deg[i] = 0;
            g_as1[i] = 0.f; g_ad1[i] = 0.f;
            g_as2[i] = 0.f; g_ad2[i] = 0.f;
        }
        if (b == 0) {
            const long long* p = (const long long*)ei;
            int bad = 0;
            #pragma unroll
            for (int k = threadIdx.x; k < 2048; k += 256) {
                long long v = p[k];
                if (v < 0 || v >= NNODES) bad = 1;
            }
            int anybad = __syncthreads_or(bad);
            if (threadIdx.x == 0) g_is64 = !anybad;
        }
    } else {
        int i = (b - NBLK_N) * blockDim.x + threadIdx.x;
        if (i < CIN * CHID) {
            int k = i / CHID, n = i % CHID;           // W1[k][n] -> w1t[n][k]
            g_w1h[n * CIN + k] = __float2half(W1[i]);
        } else if (i < CONVW_ELEMS) {
            int j = i - CIN * CHID;
            int k = j / COUT, n = j % COUT;           // W2[k][n] -> w2t[n][k]
            g_w2h[n * CHID + k] = __float2half(W2[j]);
        }
    }
    pdl_trigger();   // dependent (GEMM1) may begin launching; it pdl_waits before reads
}

// ---------------- convert + degree count ----------------
__global__ void convert_count_kernel(const void* __restrict__ ei) {
    int e = blockIdx.x * blockDim.x + threadIdx.x;
    if (e >= ETOT) return;
    int s, d;
    if (e < NEDGES) {
        if (g_is64) {
            const long long* p = (const long long*)ei;
            s = (int)p[e]; d = (int)p[NEDGES + e];
        } else {
            const int* p = (const int*)ei;
            s = p[e]; d = p[NEDGES + e];
        }
    } else {
        s = e - NEDGES; d = s;
    }
    g_esrc[e] = s;
    g_edst[e] = d;
    atomicAdd(&g_deg[d], 1);
}

// ---------------- multi-block scan ----------------
__global__ void scan_part_kernel() {
    __shared__ int sh[256];
    int i = blockIdx.x * 256 + threadIdx.x;
    sh[threadIdx.x] = (i < NNODES) ? g_deg[i] : 0;
    __syncthreads();
    #pragma unroll
    for (int st = 128; st > 0; st >>= 1) {
        if (threadIdx.x < st) sh[threadIdx.x] += sh[threadIdx.x + st];
        __syncthreads();
    }
    if (threadIdx.x == 0) g_bsum[blockIdx.x] = sh[0];
}

__global__ void scan_write_kernel() {
    __shared__ int sh[256];
    __shared__ int base_sh;
    const int t = threadIdx.x;
    const int b = blockIdx.x;
    int pv = (t < b && t < NBLK_N) ? g_bsum[t] : 0;
    sh[t] = pv;
    __syncthreads();
    #pragma unroll
    for (int st = 128; st > 0; st >>= 1) {
        if (t < st) sh[t] += sh[t + st];
        __syncthreads();
    }
    if (t == 0) base_sh = sh[0];
    __syncthreads();
    const int base = base_sh;
    __syncthreads();
    int i = b * 256 + t;
    int d = (i < NNODES) ? g_deg[i] : 0;
    sh[t] = d;
    __syncthreads();
    #pragma unroll
    for (int st = 1; st < 256; st <<= 1) {
        int v = (t >= st) ? sh[t - st] : 0;
        __syncthreads();
        sh[t] += v;
        __syncthreads();
    }
    if (i < NNODES) {
        int off = base + sh[t] - d;
        g_off[i] = off;
        g_cur[i] = off;
    }
    if (b == NBLK_N - 1 && t == 255) g_off[NNODES] = base + sh[255];
}

__global__ void fill_kernel() {
    int e = blockIdx.x * blockDim.x + threadIdx.x;
    if (e >= ETOT) return;
    int pos = atomicAdd(&g_cur[g_edst[e]], 1);
    g_srcs[pos] = g_esrc[e];
}

// ---------------- fp16 warp MMA GEMM (single combo) ----------------
// C[M x NC] = A[M x K] @ (B[NC x K])^T in fp16 x fp16 -> fp32 accum.
// CTA tile 128 x BN, 8 warps (4 m x 2 n), warp tile 32 x BN/2, mma m16n8k16.
// AFP32: A arrives as fp32 and is converted to fp16 in-register (fused conv).
// Epilogue: fp32 alpha dots + h stored as packed fp16x2.
#define KC    32
#define KPAD  40                          // 80B row stride, conflict-free fragments
#define ABYTES (128 * KPAD * 2)           // 10240

__device__ __forceinline__ void mma16816(float* c, const uint32_t* a, const uint32_t* b) {
    asm volatile(
        "mma.sync.aligned.m16n8k16.row.col.f32.f16.f16.f32 "
        "{%0,%1,%2,%3}, {%4,%5,%6,%7}, {%8,%9}, {%0,%1,%2,%3};"
        : "+f"(c[0]), "+f"(c[1]), "+f"(c[2]), "+f"(c[3])
        : "r"(a[0]), "r"(a[1]), "r"(a[2]), "r"(a[3]), "r"(b[0]), "r"(b[1]));
}

__device__ __forceinline__ uint32_t smem_u32(const void* p) {
    uint32_t a;
    asm("{ .reg .u64 t; cvta.to.shared.u64 t, %1; cvt.u32.u64 %0, t; }" : "=r"(a) : "l"(p));
    return a;
}
__device__ __forceinline__ void cp16(uint32_t dst, const void* src) {
    asm volatile("cp.async.cg.shared.global [%0], [%1], 16;" :: "r"(dst), "l"(src));
}

template <int NC, int BN, bool AFP32>
__global__ __launch_bounds__(256)
void gemm_mma_kernel(const void* __restrict__ Aarg,
                     const __half* __restrict__ Bh,
                     __half* __restrict__ Ch,
                     const float* __restrict__ avs, const float* __restrict__ avd,
                     float* __restrict__ as_out, float* __restrict__ ad_out,
                     int M, int K) {
    constexpr int NT      = BN / 16;            // n-tiles per warp
    constexpr int BBYTES  = BN * KPAD * 2;
    constexpr int BUFB    = ABYTES + BBYTES;

    extern __shared__ char smem[];
    const uint32_t sb = smem_u32(smem);

    const int tid   = threadIdx.x;
    const int wid   = tid >> 5;
    const int lane  = tid & 31;
    const int wm    = wid & 3;
    const int wn    = wid >> 2;
    const int g     = lane >> 2;
    const int t     = lane & 3;
    const int m0    = blockIdx.y * 128;
    const int n0    = blockIdx.x * BN;

    const float* Af = (const float*)Aarg;
    const __half* Ah = (const __half*)Aarg;

    pdl_trigger();          // let dependent kernel launch early
    pdl_wait();             // inputs may come from the immediately preceding kernel

    float acc[2][NT][4];
    #pragma unroll
    for (int i = 0; i < 2; i++)
        #pragma unroll
        for (int j = 0; j < NT; j++)
            #pragma unroll
            for (int q = 0; q < 4; q++) acc[i][j][q] = 0.0f;

    const int NCHUNK = K / KC;

    // fused-conversion A staging (AFP32): one thread = 16 contiguous fp32
    const int arowA = min(m0 + (tid >> 1), M - 1);
    const int halfA = tid & 1;
    float areg[AFP32 ? 16 : 1];

    auto ldgA = [&](int ch) {
        if constexpr (AFP32) {
            const float* p = Af + (size_t)arowA * K + ch * KC + halfA * 16;
            #pragma unroll
            for (int v = 0; v < 4; v++)
                *reinterpret_cast<float4*>(&areg[4 * v]) =
                    *reinterpret_cast<const float4*>(p + 4 * v);
        }
    };
    auto stsA = [&](int buf) {
        if constexpr (AFP32) {
            uint32_t hw[8];
            #pragma unroll
            for (int i = 0; i < 8; i++)
                hw[i] = pack_f16x2(areg[2 * i], areg[2 * i + 1]);
            char* base = smem + buf * BUFB + (tid >> 1) * (KPAD * 2) + halfA * 32;
            *reinterpret_cast<uint4*>(base)      = make_uint4(hw[0], hw[1], hw[2], hw[3]);
            *reinterpret_cast<uint4*>(base + 16) = make_uint4(hw[4], hw[5], hw[6], hw[7]);
        }
    };

    auto issue_chunk = [&](int ch, int buf) {
        const int kc0 = ch * KC;
        const uint32_t bbase = sb + buf * BUFB;
        if constexpr (!AFP32) {
            #pragma unroll
            for (int it = 0; it < 2; it++) {                // A: 128 rows x 4 slots
                const int idx = tid + it * 256;
                const int row = idx >> 2;
                const int c4  = idx & 3;
                const int arow = min(m0 + row, M - 1);      // clamp; garbage rows unsaved
                const size_t ao = (size_t)arow * K + kc0 + c4 * 8;
                const uint32_t so = (uint32_t)(row * (KPAD * 2) + c4 * 16);
                cp16(bbase + so, Ah + ao);
            }
        }
        #pragma unroll
        for (int it = 0; it < BN * 4 / 256; it++) {         // B: BN rows x 4 slots
            const int idx = tid + it * 256;
            const int row = idx >> 2;
            const int c4  = idx & 3;
            const size_t bo = (size_t)(n0 + row) * K + kc0 + c4 * 8;  // NC mult of BN
            const uint32_t so = (uint32_t)(row * (KPAD * 2) + c4 * 16);
            cp16(bbase + ABYTES + so, Bh + bo);
        }
        asm volatile("cp.async.commit_group;" ::: "memory");
    };

    // prologue
    ldgA(0);
    issue_chunk(0, 0);
    stsA(0);

    for (int ch = 0; ch < NCHUNK; ch++) {
        const int buf = ch & 1;
        const bool more = (ch + 1 < NCHUNK);
        if (more) {
            ldgA(ch + 1);
            issue_chunk(ch + 1, buf ^ 1);
        }
        if (more) asm volatile("cp.async.wait_group 1;" ::: "memory");
        else      asm volatile("cp.async.wait_group 0;" ::: "memory");
        __syncthreads();

        const char* pA = smem + buf * BUFB;
        const char* pB = pA + ABYTES;
        #pragma unroll
        for (int ks = 0; ks < KC / 16; ks++) {
            const int kb = ks * 16;
            uint32_t afrag[2][4];
            #pragma unroll
            for (int mt = 0; mt < 2; mt++) {
                const int r0 = wm * 32 + mt * 16 + g;
                const char* q0 = pA + r0 * (KPAD * 2) + (kb + 2 * t) * 2;
                const char* q1 = pA + (r0 + 8) * (KPAD * 2) + (kb + 2 * t) * 2;
                afrag[mt][0] = *reinterpret_cast<const uint32_t*>(q0);
                afrag[mt][1] = *reinterpret_cast<const uint32_t*>(q1);
                afrag[mt][2] = *reinterpret_cast<const uint32_t*>(q0 + 16);
                afrag[mt][3] = *reinterpret_cast<const uint32_t*>(q1 + 16);
            }
            uint32_t bfrag[NT][2];
            #pragma unroll
            for (int nt = 0; nt < NT; nt++) {
                const int n = wn * (BN / 2) + nt * 8 + g;
                const char* q = pB + n * (KPAD * 2) + (kb + 2 * t) * 2;
                bfrag[nt][0] = *reinterpret_cast<const uint32_t*>(q);
                bfrag[nt][1] = *reinterpret_cast<const uint32_t*>(q + 16);
            }
            #pragma unroll
            for (int mt = 0; mt < 2; mt++)
                #pragma unroll
                for (int nt = 0; nt < NT; nt++)
                    mma16816(acc[mt][nt], afrag[mt], bfrag[nt]);
        }
        if (more) stsA(buf ^ 1);   // visible after next iteration's __syncthreads
        __syncthreads();           // buf free for reuse
    }

    // ---- epilogue: fp16x2 store of h + fused fp32 alpha dots ----
    float sa[4] = {0.f, 0.f, 0.f, 0.f};   // rows: wm*32 + {0,8,16,24} + g
    float da[4] = {0.f, 0.f, 0.f, 0.f};
    #pragma unroll
    for (int mt = 0; mt < 2; mt++) {
        const int r0 = m0 + wm * 32 + mt * 16 + g;
        #pragma unroll
        for (int nt = 0; nt < NT; nt++) {
            const int col = n0 + wn * (BN / 2) + nt * 8 + 2 * t;
            const float v0 = avs[col], v1 = avs[col + 1];
            const float u0 = avd[col], u1 = avd[col + 1];
            sa[2 * mt]     += acc[mt][nt][0] * v0 + acc[mt][nt][1] * v1;
            da[2 * mt]     += acc[mt][nt][0] * u0 + acc[mt][nt][1] * u1;
            sa[2 * mt + 1] += acc[mt][nt][2] * v0 + acc[mt][nt][3] * v1;
            da[2 * mt + 1] += acc[mt][nt][2] * u0 + acc[mt][nt][3] * u1;
            if (r0 < M)
                *reinterpret_cast<uint32_t*>(&Ch[(size_t)r0 * NC + col]) =
                    pack_f16x2(acc[mt][nt][0], acc[mt][nt][1]);
            if (r0 + 8 < M)
                *reinterpret_cast<uint32_t*>(&Ch[(size_t)(r0 + 8) * NC + col]) =
                    pack_f16x2(acc[mt][nt][2], acc[mt][nt][3]);
        }
    }
    #pragma unroll
    for (int q = 0; q < 4; q++) {
        sa[q] += __shfl_xor_sync(0xffffffffu, sa[q], 1);
        sa[q] += __shfl_xor_sync(0xffffffffu, sa[q], 2);
        da[q] += __shfl_xor_sync(0xffffffffu, da[q], 1);
        da[q] += __shfl_xor_sync(0xffffffffu, da[q], 2);
    }
    if (t == 0) {
        #pragma unroll
        for (int q = 0; q < 4; q++) {
            const int r = m0 + wm * 32 + q * 8 + g;
            if (r < M) {
                atomicAdd(&as_out[r], sa[q]);
                atomicAdd(&ad_out[r], da[q]);
            }
        }
    }
}

// ---------------- fused softmax + aggregation: 2 edge-groups per dst block ----------------
// blockDim = 2*(C/4). Group g (of 2) processes edges jj = g (mod 2) with its own
// fp32 accumulators (doubles MLP, halves syncs); smem combine at the end.
// Gathers fp16 (uint2 = 4 channels/thread). No max-subtraction (overflow-safe).
template <int C, bool F16OUT>
__global__ void aggregate_kernel(const __half* __restrict__ hh,
                                 const float* __restrict__ bias,
                                 const float* __restrict__ as_in,
                                 const float* __restrict__ ad_in,
                                 float* __restrict__ out) {
    constexpr int TH = C / 4;      // channel-group threads
    constexpr int NB = 2 * TH;     // block size
    __shared__ float ws[NB];
    __shared__ int   ss[NB];
    __shared__ float racc[4 * TH];
    __shared__ float rden;
    const int d   = blockIdx.x;
    const int tid = threadIdx.x;
    const int tc  = tid & (TH - 1);
    const int grp = tid / TH;      // 0 or 1

    pdl_trigger();
    // PDL prologue: CSR data (g_off/g_srcs) is guaranteed by the event edge,
    // not by the immediately preceding kernel, so stage it before pdl_wait.
    const int beg = g_off[d];
    const int end = g_off[d + 1];
    float ad = 0.0f;
    bool waited = false;

    float4 a0 = make_float4(0.f, 0.f, 0.f, 0.f);
    float4 a1 = make_float4(0.f, 0.f, 0.f, 0.f);
    float dn = 0.0f;
    for (int cbeg = beg; cbeg < end; cbeg += NB) {
        const int nchunk = min(NB, end - cbeg);
        __syncthreads();
        int s = -1;
        if (tid < nchunk) {
            s = g_srcs[cbeg + tid];
            ss[tid] = s;
        }
        if (!waited) {           // first iteration: wait for h / as / ad producers
            pdl_wait();
            ad = ad_in[d];
            waited = true;
        }
        if (tid < nchunk) {
            float tt = as_in[s] + ad;
            float l = tt > 0.0f ? tt : NEG_SLOPE * tt;
            ws[tid] = __expf(l);
        }
        __syncthreads();
        int jj = grp;
        for (; jj + 2 < nchunk; jj += 4) {    // this group's pairs (jj, jj+2)
            const float w0 = ws[jj];
            const float w1 = ws[jj + 2];
            const uint2 p0 = *reinterpret_cast<const uint2*>(
                &hh[(size_t)ss[jj] * C + 4 * tc]);
            const uint2 p1 = *reinterpret_cast<const uint2*>(
                &hh[(size_t)ss[jj + 2] * C + 4 * tc]);
            const float2 x01 = unpack_f16x2(p0.x), x23 = unpack_f16x2(p0.y);
            const float2 y01 = unpack_f16x2(p1.x), y23 = unpack_f16x2(p1.y);
            dn += w0 + w1;
            a0.x += w0 * x01.x;  a1.x += w1 * y01.x;
            a0.y += w0 * x01.y;  a1.y += w1 * y01.y;
            a0.z += w0 * x23.x;  a1.z += w1 * y23.x;
            a0.w += w0 * x23.y;  a1.w += w1 * y23.y;
        }
        for (; jj < nchunk; jj += 2) {
            const float w = ws[jj];
            const uint2 p = *reinterpret_cast<const uint2*>(
                &hh[(size_t)ss[jj] * C + 4 * tc]);
            const float2 x01 = unpack_f16x2(p.x), x23 = unpack_f16x2(p.y);
            dn += w;
            a0.x += w * x01.x; a0.y += w * x01.y;
            a0.z += w * x23.x; a0.w += w * x23.y;
        }
    }

    // combine the two edge-groups
    float4 acc;
    acc.x = a0.x + a1.x; acc.y = a0.y + a1.y;
    acc.z = a0.z + a1.z; acc.w = a0.w + a1.w;
    __syncthreads();
    if (grp == 1) {
        racc[4 * tc + 0] = acc.x;
        racc[4 * tc + 1] = acc.y;
        racc[4 * tc + 2] = acc.z;
        racc[4 * tc + 3] = acc.w;
        if (tc == 0) rden = dn;
    }
    __syncthreads();
    if (grp == 0) {
        acc.x += racc[4 * tc + 0];
        acc.y += racc[4 * tc + 1];
        acc.z += racc[4 * tc + 2];
        acc.w += racc[4 * tc + 3];
        const float inv = 1.0f / (dn + rden);
        const float4 bv = *reinterpret_cast<const float4*>(&bias[4 * tc]);
        float4 r;
        r.x = acc.x * inv + bv.x;
        r.y = acc.y * inv + bv.y;
        r.z = acc.z * inv + bv.z;
        r.w = acc.w * inv + bv.w;
        if (F16OUT) {
            r.x = fmaxf(r.x, 0.f); r.y = fmaxf(r.y, 0.f);
            r.z = fmaxf(r.z, 0.f); r.w = fmaxf(r.w, 0.f);
            *reinterpret_cast<uint2*>(&g_t[(size_t)d * C + 4 * tc]) =
                make_uint2(pack_f16x2(r.x, r.y), pack_f16x2(r.z, r.w));
        } else {
            *reinterpret_cast<float4*>(&out[(size_t)d * C + 4 * tc]) = r;
        }
    }
}

// ---------------- launch ----------------
extern "C" void kernel_launch(void* const* d_in, const int* in_sizes, int n_in,
                              void* d_out, int out_size) {
    const float* x   = (const float*)d_in[0];
    const void*  ei  = (const void*)d_in[1];
    const float* W1  = (const float*)d_in[2];
    const float* as1 = (const float*)d_in[3];
    const float* ad1 = (const float*)d_in[4];
    const float* b1  = (const float*)d_in[5];
    const float* W2  = (const float*)d_in[6];
    const float* as2 = (const float*)d_in[7];
    const float* ad2 = (const float*)d_in[8];
    const float* b2  = (const float*)d_in[9];
    float* out = (float*)d_out;

    float *pas1, *pad1, *pas2, *pad2;
    cudaGetSymbolAddress((void**)&pas1, g_as1);
    cudaGetSymbolAddress((void**)&pad1, g_ad1);
    cudaGetSymbolAddress((void**)&pas2, g_as2);
    cudaGetSymbolAddress((void**)&pad2, g_ad2);
    __half *hh, *tt, *w1h, *w2h;
    cudaGetSymbolAddress((void**)&hh, g_hh);
    cudaGetSymbolAddress((void**)&tt, g_t);
    cudaGetSymbolAddress((void**)&w1h, g_w1h);
    cudaGetSymbolAddress((void**)&w2h, g_w2h);

    constexpr int SMEM64 = 2 * (ABYTES + 64 * KPAD * 2);   // 30720

    // one-time host objects (no device memory involved)
    static cudaStream_t sCSR = nullptr;
    static cudaEvent_t evFork = nullptr, evCSR = nullptr;
    if (sCSR == nullptr) {
        cudaFuncSetAttribute(gemm_mma_kernel<CHID, 64, true>,
                             cudaFuncAttributeMaxDynamicSharedMemorySize, SMEM64);
        cudaFuncSetAttribute(gemm_mma_kernel<COUT, 64, false>,
                             cudaFuncAttributeMaxDynamicSharedMemorySize, SMEM64);
        cudaStreamCreateWithFlags(&sCSR, cudaStreamNonBlocking);
        cudaEventCreateWithFlags(&evFork, cudaEventDisableTiming);
        cudaEventCreateWithFlags(&evCSR, cudaEventDisableTiming);
    }

    const int TPB = 256;
    const int nblk_edges = (ETOT + TPB - 1) / TPB;
    const int MTILES = (NNODES + 127) / 128;   // 157

    // PDL launch config (chained: setup -> gemm1 -> agg1 -> gemm2 -> agg2)
    cudaLaunchAttribute pdlAttr[1];
    pdlAttr[0].id = cudaLaunchAttributeProgrammaticStreamSerialization;
    pdlAttr[0].val.programmaticStreamSerializationAllowed = 1;

    // ---- stream 0: setup (init + detect + weight conversion) ----
    setup_kernel<<<NBLK_N + NBLK_W, TPB>>>(ei, W1, W2);
    cudaEventRecord(evFork, 0);

    // ---- CSR branch (sCSR) ----
    cudaStreamWaitEvent(sCSR, evFork, 0);
    convert_count_kernel<<<nblk_edges, TPB, 0, sCSR>>>(ei);
    scan_part_kernel<<<NBLK_N, 256, 0, sCSR>>>();
    scan_write_kernel<<<NBLK_N, 256, 0, sCSR>>>();
    fill_kernel<<<nblk_edges, TPB, 0, sCSR>>>();
    cudaEventRecord(evCSR, sCSR);

    // ---- main: GEMM1 (PDL after setup; fp32 x converted in-register) ----
    {
        cudaLaunchConfig_t cfg = {};
        cfg.gridDim = dim3(CHID / 64, MTILES);
        cfg.blockDim = dim3(256, 1, 1);
        cfg.dynamicSmemBytes = SMEM64;
        cfg.stream = 0;
        cfg.attrs = pdlAttr;
        cfg.numAttrs = 1;
        int M = NNODES, K = CIN;
        cudaLaunchKernelEx(&cfg, gemm_mma_kernel<CHID, 64, true>,
                           (const void*)x, (const __half*)w1h,
                           (__half*)hh, (const float*)as1, (const float*)ad1,
                           (float*)pas1, (float*)pad1, M, K);
    }

    // ---- join CSR, aggregate1 (PDL after gemm1; CSR via hard event edge) ----
    cudaStreamWaitEvent(0, evCSR, 0);
    {
        cudaLaunchConfig_t cfg = {};
        cfg.gridDim = dim3(NNODES, 1, 1);
        cfg.blockDim = dim3(CHID / 2, 1, 1);   // 2 * (C/4)
        cfg.dynamicSmemBytes = 0;
        cfg.stream = 0;
        cfg.attrs = pdlAttr;
        cfg.numAttrs = 1;
        cudaLaunchKernelEx(&cfg, aggregate_kernel<CHID, true>,
                           (const __half*)hh, (const float*)b1,
                           (const float*)pas1, (const float*)pad1, (float*)nullptr);
    }

    // ---- layer 2 (PDL chained: agg1 -> gemm2 -> agg2) ----
    {
        cudaLaunchConfig_t cfg = {};
        cfg.gridDim = dim3(COUT / 64, MTILES);
        cfg.blockDim = dim3(256, 1, 1);
        cfg.dynamicSmemBytes = SMEM64;
        cfg.stream = 0;
        cfg.attrs = pdlAttr;
        cfg.numAttrs = 1;
        int M = NNODES, K = CHID;
        cudaLaunchKernelEx(&cfg, gemm_mma_kernel<COUT, 64, false>,
                           (const void*)tt, (const __half*)w2h,
                           (__half*)hh, (const float*)as2, (const float*)ad2,
                           (float*)pas2, (float*)pad2, M, K);
    }
    {
        cudaLaunchConfig_t cfg = {};
        cfg.gridDim = dim3(NNODES, 1, 1);
        cfg.blockDim = dim3(COUT / 2, 1, 1);   // 2 * (C/4)
        cfg.dynamicSmemBytes = 0;
        cfg.stream = 0;
        cfg.attrs = pdlAttr;
        cfg.numAttrs = 1;
        cudaLaunchKernelEx(&cfg, aggregate_kernel<COUT, false>,
                           (const __half*)hh, (const float*)b2,
                           (const float*)pas2, (const float*)pad2, (float*)out);
    }
}